// round 13
// baseline (speedup 1.0000x reference)
#include <cuda_runtime.h>
#include <math.h>

typedef unsigned long long u64;

__device__ __forceinline__ u64 pack2(float v) {
    u64 r; asm("mov.b64 %0, {%1, %1};" : "=l"(r) : "f"(v)); return r;
}
__device__ __forceinline__ u64 ffma2(u64 a, u64 b, u64 c) {
    u64 d; asm("fma.rn.f32x2 %0, %1, %2, %3;" : "=l"(d) : "l"(a), "l"(b), "l"(c)); return d;
}
__device__ __forceinline__ float2 unpack2(u64 a) {
    float2 f; asm("mov.b64 {%0, %1}, %2;" : "=f"(f.x), "=f"(f.y) : "l"(a)); return f;
}

// ---------------------------------------------------------------------------
// Scratch arena. Activations halo-padded: dim D stored as P=D+2, interior
// voxel (z,y,x) at ((z+1)*P+(y+1))*P+(x+1). Halos are NEVER written -> stay 0.
// ---------------------------------------------------------------------------
constexpr int OX0  = 0;
constexpr int OZ1  = 2299968;
constexpr int OZ2  = 4815424;
constexpr int OZ3  = 5561920;
constexpr int OZ4  = 5817920;
constexpr int OZ5  = 7310912;
constexpr int OM0P = 11505216;
constexpr int OM1  = 12080208;
constexpr int OM2  = 12145744;
constexpr int OM3  = 12153936;
constexpr int OM4  = 12154960;
constexpr int OM5  = 12163152;
constexpr int OW1  = 12228688;
constexpr int OW2  = 12236880;
constexpr int OW3  = 12367952;
constexpr int OTW1 = 12892240;
constexpr int OTW2 = 13940816;
constexpr int OFW  = 14465104;
constexpr int OST  = 14467152;
constexpr int OPB  = 14468452;
constexpr int TOT_SCRATCH = 22857216;

__device__ __align__(16) float g_scratch[TOT_SCRATCH];

// weight transposes + stats zeroing
__global__ void k_trans_all(const float* __restrict__ w1, const float* __restrict__ w2,
                            const float* __restrict__ w3, const float* __restrict__ tw1,
                            const float* __restrict__ tw2, const float* __restrict__ fw,
                            float* __restrict__ S) {
    int idx = blockIdx.x * 256 + threadIdx.x;
    if (idx < 5 * 260) S[OST + idx] = 0.f;
    const float* src; float* dst; int CI, CO, i = idx;
    if (i < 8192)            { src = w1;  dst = S + OW1;  CI = 4;   CO = 32;  }
    else if ((i -= 8192)  < 131072)  { src = w2;  dst = S + OW2;  CI = 32;  CO = 64;  }
    else if ((i -= 131072) < 524288) { src = w3;  dst = S + OW3;  CI = 64;  CO = 128; }
    else if ((i -= 524288) < 1048576){ src = tw1; dst = S + OTW1; CI = 128; CO = 128; }
    else if ((i -= 1048576)< 524288) { src = tw2; dst = S + OTW2; CI = 128; CO = 64;  }
    else if ((i -= 524288) < 2048)   { S[OFW + (i % 64) * 32 + i / 64] = fw[i]; return; }
    else return;
    int t = i & 63, ci = (i >> 6) % CI, co = i / (64 * CI);
    dst[(t * CI + ci) * CO + co] = src[i];
}

// masked input into padded x0 + padded m0p
__global__ void k_pre(const float* __restrict__ feat, const float* __restrict__ mask,
                      float* __restrict__ x0, float* __restrict__ m0p) {
    int v = blockIdx.x * 256 + threadIdx.x;
    float m = mask[v] > 0.5f ? 1.f : 0.f;
    int b = v >> 18, r = v & 262143;
    int z = r >> 12, y = (r >> 6) & 63, x = r & 63;
    int poff = ((z + 1) * 66 + (y + 1)) * 66 + (x + 1);
    m0p[b * 287496 + poff] = m;
#pragma unroll
    for (int c = 0; c < 4; c++)
        x0[(b * 4 + c) * 287496 + poff] = feat[(b * 4 + c) * 262144 + r] * m;
}

// mask dilation 64^3->32^3 from PADDED m0p, branch-free, 2 voxels/thread
__global__ void k_maskd64p(const float* __restrict__ m0p, float* __restrict__ mo,
                           float* __restrict__ cnt) {
    int v = blockIdx.x * 256 + threadIdx.x;
    int b = v / 16384, rp = v % 16384;
    int r = 2 * rp;
    int oz = r >> 10, oy = (r >> 5) & 31, ox = r & 31;
    const float* base = m0p + b * 287496 + (2 * oz) * 4356 + (2 * oy) * 66 + 2 * ox;
    float sA = 0.f, sB = 0.f;
#pragma unroll
    for (int tz = 0; tz < 4; tz++)
#pragma unroll
        for (int ty = 0; ty < 4; ty++) {
            const float* p = base + tz * 4356 + ty * 66;
            float w0 = __ldg(p), w1 = __ldg(p + 1), w2 = __ldg(p + 2);
            float w3 = __ldg(p + 3), w4 = __ldg(p + 4), w5 = __ldg(p + 5);
            float c = w2 + w3;
            sA += w0 + w1 + c;
            sB += c + w4 + w5;
        }
    float aA = sA > 0.f ? 1.f : 0.f, aB = sB > 0.f ? 1.f : 0.f;
    mo[b * 32768 + r] = aA;
    mo[b * 32768 + r + 1] = aB;
    float s = aA + aB;
    for (int o = 16; o; o >>= 1) s += __shfl_xor_sync(0xffffffffu, s, o);
    if ((threadIdx.x & 31) == 0) atomicAdd(cnt, s);
}

// ---------------------------------------------------------------------------
// Mask dilation device bodies (used by fused kernels' extra blocks)
// ---------------------------------------------------------------------------
template <int DI, int DO>
__device__ __forceinline__ void maskd_fwd_body(int blk, const float* __restrict__ mi,
                                               float* __restrict__ mo, float* __restrict__ cnt) {
    const int DO3 = DO * DO * DO, DI2 = DI * DI, DI3 = DI * DI * DI;
    int v = blk * 256 + threadIdx.x;
    int b = v / DO3, r = v % DO3;
    int oz = r / (DO * DO), oy = (r / DO) % DO, ox = r % DO;
    float m = 0.f;
    for (int tz = 0; tz < 4; tz++) {
        int iz = 2 * oz - 1 + tz;
        if ((unsigned)iz >= DI) continue;
        for (int ty = 0; ty < 4; ty++) {
            int iy = 2 * oy - 1 + ty;
            if ((unsigned)iy >= DI) continue;
            const float* p = mi + b * DI3 + iz * DI2 + iy * DI;
            for (int tx = 0; tx < 4; tx++) {
                int ix = 2 * ox - 1 + tx;
                if ((unsigned)ix < DI) m += p[ix];
            }
        }
    }
    float act = m > 0.f ? 1.f : 0.f;
    mo[v] = act;
    float s = act;
    for (int o = 16; o; o >>= 1) s += __shfl_xor_sync(0xffffffffu, s, o);
    if ((threadIdx.x & 31) == 0) atomicAdd(cnt, s);
}

template <int DI, int DO>
__device__ __forceinline__ void maskd_t_body(int blk, const float* __restrict__ mi,
                                             float* __restrict__ mo, float* __restrict__ cnt) {
    const int DO3 = DO * DO * DO, DI2 = DI * DI, DI3 = DI * DI * DI;
    int v = blk * 256 + threadIdx.x;
    int b = v / DO3, r = v % DO3;
    int oz = r / (DO * DO), oy = (r / DO) % DO, ox = r % DO;
    int izl[2], iyl[2], ixl[2];
    izl[0] = oz >> 1; izl[1] = (oz & 1) ? (oz >> 1) + 1 : (oz >> 1) - 1;
    iyl[0] = oy >> 1; iyl[1] = (oy & 1) ? (oy >> 1) + 1 : (oy >> 1) - 1;
    ixl[0] = ox >> 1; ixl[1] = (ox & 1) ? (ox >> 1) + 1 : (ox >> 1) - 1;
    float m = 0.f;
#pragma unroll
    for (int jz = 0; jz < 2; jz++) {
        int iz = izl[jz];
        if ((unsigned)iz >= DI) continue;
#pragma unroll
        for (int jy = 0; jy < 2; jy++) {
            int iy = iyl[jy];
            if ((unsigned)iy >= DI) continue;
#pragma unroll
            for (int jx = 0; jx < 2; jx++) {
                int ix = ixl[jx];
                if ((unsigned)ix < DI) m += mi[b * DI3 + iz * DI2 + iy * DI + ix];
            }
        }
    }
    float act = m > 0.f ? 1.f : 0.f;
    mo[v] = act;
    float s = act;
    for (int o = 16; o; o >>= 1) s += __shfl_xor_sync(0xffffffffu, s, o);
    if ((threadIdx.x & 31) == 0) atomicAdd(cnt, s);
}

// ---------------------------------------------------------------------------
// Forward conv, 4 adjacent output voxels x NCO co per thread.
// ---------------------------------------------------------------------------
template <int CI, int CO, int DI, int DO, int SPLIT, bool FULLW, int NCO>
__global__ void __launch_bounds__(256) k_conv_fwd2(
    const float* __restrict__ x, const float* __restrict__ wT,
    const float* __restrict__ bias, const float* __restrict__ mo,
    float* __restrict__ zout, float* __restrict__ stats) {
    constexpr int PI = DI + 2, PO = DO + 2;
    constexpr int PI2 = PI * PI, PI3 = PI2 * PI, PO3 = PO * PO * PO;
    constexpr int DO3 = DO * DO * DO, QDO3 = DO3 / 4;
    constexpr int NTAP = FULLW ? 64 : ((SPLIT == 16) ? 4 : 16);
    constexpr int NP = NCO / 2;
    __shared__ __align__(16) float sw[NTAP * CI * NCO];
    const int co0 = blockIdx.y * NCO;
    const int v = blockIdx.x * 256 + threadIdx.x;
    const int b = v / QDO3, rp = v % QDO3;
    const int r = 4 * rp;
    const int oz = r / (DO * DO), oy = (r / DO) % DO, ox = r % DO;
    u64 acc[4][NP];
#pragma unroll
    for (int vv = 0; vv < 4; vv++)
#pragma unroll
        for (int p = 0; p < NP; p++) acc[vv][p] = 0ull;
    const float* xbase = x + (b * CI) * PI3 + (2 * oz) * PI2 + (2 * oy) * PI + 2 * ox;

    auto stage = [&](int t0, int ntap) {
        for (int i = threadIdx.x; i < ntap * CI * NCO; i += 256) {
            int k = i % NCO, ci = (i / NCO) % CI, s = i / (NCO * CI);
            sw[i] = wT[((t0 + s) * CI + ci) * CO + co0 + k];
        }
    };
    auto body = [&](int tz, int ty, const float* swrow) {
        const float* xr = xbase + tz * PI2 + ty * PI;
#pragma unroll 4
        for (int ci = 0; ci < CI; ci++) {
            const float* xp = xr + ci * PI3;
            float2 q0 = *reinterpret_cast<const float2*>(xp);
            float2 q1 = *reinterpret_cast<const float2*>(xp + 2);
            float2 q2 = *reinterpret_cast<const float2*>(xp + 4);
            float2 q3 = *reinterpret_cast<const float2*>(xp + 6);
            float2 q4 = *reinterpret_cast<const float2*>(xp + 8);
            u64 p[10];
            p[0] = pack2(q0.x); p[1] = pack2(q0.y); p[2] = pack2(q1.x);
            p[3] = pack2(q1.y); p[4] = pack2(q2.x); p[5] = pack2(q2.y);
            p[6] = pack2(q3.x); p[7] = pack2(q3.y); p[8] = pack2(q4.x);
            p[9] = pack2(q4.y);
#pragma unroll
            for (int tx = 0; tx < 4; tx++) {
                const float* wp = swrow + (tx * CI + ci) * NCO;
                u64 w[NP];
#pragma unroll
                for (int q = 0; q < NCO / 4; q++) {
                    ulonglong2 ww = reinterpret_cast<const ulonglong2*>(wp)[q];
                    w[2 * q] = ww.x; w[2 * q + 1] = ww.y;
                }
#pragma unroll
                for (int vv = 0; vv < 4; vv++)
#pragma unroll
                    for (int j = 0; j < NP; j++)
                        acc[vv][j] = ffma2(p[2 * vv + tx], w[j], acc[vv][j]);
            }
        }
    };

    if constexpr (SPLIT == 1) {
        if constexpr (FULLW) {
            stage(0, 64);
            __syncthreads();
            for (int tz = 0; tz < 4; tz++)
                for (int ty = 0; ty < 4; ty++)
                    body(tz, ty, sw + (tz * 16 + ty * 4) * CI * NCO);
        } else {
            for (int tz = 0; tz < 4; tz++) {
                __syncthreads();
                stage(tz * 16, 16);
                __syncthreads();
                for (int ty = 0; ty < 4; ty++) body(tz, ty, sw + (ty * 4) * CI * NCO);
            }
        }
    } else if constexpr (SPLIT == 4) {
        const int tz = blockIdx.z;
        stage(tz * 16, 16);
        __syncthreads();
        for (int ty = 0; ty < 4; ty++) body(tz, ty, sw + (ty * 4) * CI * NCO);
    } else {
        const int tz = blockIdx.z >> 2, ty = blockIdx.z & 3;
        stage(tz * 16 + ty * 4, 4);
        __syncthreads();
        body(tz, ty, sw);
    }

    if constexpr (SPLIT == 1) {
        __shared__ float ssum[NCO], ssq[NCO];
        float mk[4];
#pragma unroll
        for (int vv = 0; vv < 4; vv++) mk[vv] = mo[b * DO3 + r + vv];
        const int poffA = ((oz + 1) * PO + (oy + 1)) * PO + (ox + 1);
        float sN[NCO], qN[NCO];
#pragma unroll
        for (int p = 0; p < NP; p++) {
            float bi0 = bias[co0 + 2 * p], bi1 = bias[co0 + 2 * p + 1];
            float y0[4], y1[4];
#pragma unroll
            for (int vv = 0; vv < 4; vv++) {
                float2 a = unpack2(acc[vv][p]);
                float t0 = (a.x + bi0) * mk[vv];
                float t1 = (a.y + bi1) * mk[vv];
                y0[vv] = t0 >= 0.f ? t0 : 0.01f * t0;
                y1[vv] = t1 >= 0.f ? t1 : 0.01f * t1;
            }
            float* zp0 = zout + (b * CO + co0 + 2 * p) * PO3 + poffA;
            float* zp1 = zp0 + PO3;
#pragma unroll
            for (int vv = 0; vv < 4; vv++) { zp0[vv] = y0[vv]; zp1[vv] = y1[vv]; }
            sN[2*p]   = y0[0] + y0[1] + y0[2] + y0[3];
            qN[2*p]   = y0[0]*y0[0] + y0[1]*y0[1] + y0[2]*y0[2] + y0[3]*y0[3];
            sN[2*p+1] = y1[0] + y1[1] + y1[2] + y1[3];
            qN[2*p+1] = y1[0]*y1[0] + y1[1]*y1[1] + y1[2]*y1[2] + y1[3]*y1[3];
        }
        __syncthreads();
        if (threadIdx.x < NCO) { ssum[threadIdx.x] = 0.f; ssq[threadIdx.x] = 0.f; }
        __syncthreads();
#pragma unroll
        for (int k = 0; k < NCO; k++) {
            float s = sN[k], q = qN[k];
            for (int o = 16; o; o >>= 1) {
                s += __shfl_xor_sync(0xffffffffu, s, o);
                q += __shfl_xor_sync(0xffffffffu, q, o);
            }
            if ((threadIdx.x & 31) == 0) { atomicAdd(&ssum[k], s); atomicAdd(&ssq[k], q); }
        }
        __syncthreads();
        if (threadIdx.x < NCO)
            atomicAdd(&stats[co0 + threadIdx.x], ssum[threadIdx.x]);
        else if (threadIdx.x < 2 * NCO)
            atomicAdd(&stats[CO + co0 + threadIdx.x - NCO], ssq[threadIdx.x - NCO]);
    } else {
        float* pb = zout + ((blockIdx.z * 2 + b) * CO) * DO3 + r;
#pragma unroll
        for (int p = 0; p < NP; p++) {
            float2 a0 = unpack2(acc[0][p]);
            float2 a1 = unpack2(acc[1][p]);
            float2 a2 = unpack2(acc[2][p]);
            float2 a3 = unpack2(acc[3][p]);
            *reinterpret_cast<float4*>(pb + (co0 + 2 * p) * DO3)
                = make_float4(a0.x, a1.x, a2.x, a3.x);
            *reinterpret_cast<float4*>(pb + (co0 + 2 * p + 1) * DO3)
                = make_float4(a0.y, a1.y, a2.y, a3.y);
        }
    }
}

// ---------------------------------------------------------------------------
// Transpose conv, 2 adjacent input voxels x NCO co per thread, parity classes.
// ---------------------------------------------------------------------------
template <int CI, int CO, int DI, bool PADOUT, int SLOTS, int NCO>
__global__ void __launch_bounds__(256) k_conv_t2(
    const float* __restrict__ x, const float* __restrict__ wT,
    const float* __restrict__ bias, const float* __restrict__ mo,
    float* __restrict__ zout, float* __restrict__ stats) {
    constexpr int DO = 2 * DI, PI = DI + 2, PO = DO + 2;
    constexpr int PI2 = PI * PI, PI3 = PI2 * PI;
    constexpr int DI2 = DI * DI, DI3 = DI2 * DI, DO3 = DO * DO * DO;
    constexpr int PO3 = PO * PO * PO, HDI3 = DI3 / 2;
    constexpr int NJP = 4 / SLOTS;
    constexpr int NP = NCO / 2;
    __shared__ __align__(16) float sw[2 * CI * NCO];
    const int cls = (SLOTS == 1) ? blockIdx.z : (blockIdx.z & 7);
    const int jp0 = (SLOTS == 1) ? 0 : (blockIdx.z >> 3);
    const int pz = (cls >> 2) & 1, py = (cls >> 1) & 1, px = cls & 1;
    const int cog = blockIdx.y * NCO;
    const int v = blockIdx.x * 256 + threadIdx.x;
    const int b = v / HDI3, rp = v % HDI3;
    const int r = 2 * rp;
    const int zi = r / DI2, yi = (r / DI) % DI, xi = r % DI;

    u64 aA[NP], aB[NP];
#pragma unroll
    for (int k = 0; k < NP; k++) { aA[k] = 0ull; aB[k] = 0ull; }

    const int sxp = (px ? xi : xi - 1) + 1;

    for (int jj = 0; jj < NJP; jj++) {
        const int jp = jp0 * NJP + jj;
        const int jz = jp >> 1, jy = jp & 1;
        const int tz = pz ? 2 - 2 * jz : 1 + 2 * jz;
        const int ty = py ? 2 - 2 * jy : 1 + 2 * jy;
        if (jj) __syncthreads();
        for (int i = threadIdx.x; i < 2 * CI * NCO; i += 256) {
            int k = i % NCO, ci = (i / NCO) % CI, jx = i / (NCO * CI);
            int tx = px ? 2 - 2 * jx : 1 + 2 * jx;
            sw[i] = wT[((tz * 16 + ty * 4 + tx) * CI + ci) * CO + cog + k];
        }
        __syncthreads();
        const int iz = pz ? zi + jz : zi - jz;
        const int iy = py ? yi + jy : yi - jy;
        const float* xr = x + (b * CI) * PI3 + (iz + 1) * PI2 + (iy + 1) * PI + sxp;
#pragma unroll 4
        for (int ci = 0; ci < CI; ci++) {
            const float* xp = xr + ci * PI3;
            u64 p0 = pack2(xp[0]), p1 = pack2(xp[1]), p2 = pack2(xp[2]);
#pragma unroll
            for (int jx = 0; jx < 2; jx++) {
                const float* wp = sw + (jx * CI + ci) * NCO;
                u64 w[NP];
#pragma unroll
                for (int q = 0; q < NCO / 4; q++) {
                    ulonglong2 ww = reinterpret_cast<const ulonglong2*>(wp)[q];
                    w[2 * q] = ww.x; w[2 * q + 1] = ww.y;
                }
                u64 xA, xB;
                if (jx == 0) { xA = px ? p0 : p1; xB = px ? p1 : p2; }
                else         { xA = px ? p1 : p0; xB = px ? p2 : p1; }
#pragma unroll
                for (int j = 0; j < NP; j++) {
                    aA[j] = ffma2(xA, w[j], aA[j]);
                    aB[j] = ffma2(xB, w[j], aB[j]);
                }
            }
        }
    }

    const int oz = 2 * zi + pz, oy = 2 * yi + py;
    const int oxA = 2 * xi + px;
    const int roA = (oz * DO + oy) * DO + oxA;

    if constexpr (SLOTS == 1) {
        __shared__ float ssum[NCO], ssq[NCO];
        const float mA = mo[b * DO3 + roA], mB = mo[b * DO3 + roA + 2];
        const int ooffA = PADOUT ? ((oz + 1) * PO + (oy + 1)) * PO + (oxA + 1) : roA;
        const int ostr  = PADOUT ? PO3 : DO3;
        float zsA[NCO], zsB[NCO];
#pragma unroll
        for (int p = 0; p < NP; p++) {
            float2 a = unpack2(aA[p]);
            float2 bb = unpack2(aB[p]);
            float bi0 = bias[cog + 2 * p], bi1 = bias[cog + 2 * p + 1];
            float yA0 = (a.x + bi0) * mA, yA1 = (a.y + bi1) * mA;
            float yB0 = (bb.x + bi0) * mB, yB1 = (bb.y + bi1) * mB;
            zsA[2*p]   = yA0 >= 0.f ? yA0 : 0.01f * yA0;
            zsA[2*p+1] = yA1 >= 0.f ? yA1 : 0.01f * yA1;
            zsB[2*p]   = yB0 >= 0.f ? yB0 : 0.01f * yB0;
            zsB[2*p+1] = yB1 >= 0.f ? yB1 : 0.01f * yB1;
            float* zp0 = zout + (b * CO + cog + 2 * p) * ostr + ooffA;
            float* zp1 = zout + (b * CO + cog + 2 * p + 1) * ostr + ooffA;
            zp0[0] = zsA[2*p];   zp0[2] = zsB[2*p];
            zp1[0] = zsA[2*p+1]; zp1[2] = zsB[2*p+1];
        }
        __syncthreads();
        if (threadIdx.x < NCO) { ssum[threadIdx.x] = 0.f; ssq[threadIdx.x] = 0.f; }
        __syncthreads();
#pragma unroll
        for (int k = 0; k < NCO; k++) {
            float s = zsA[k] + zsB[k];
            float q = zsA[k] * zsA[k] + zsB[k] * zsB[k];
            for (int o = 16; o; o >>= 1) {
                s += __shfl_xor_sync(0xffffffffu, s, o);
                q += __shfl_xor_sync(0xffffffffu, q, o);
            }
            if ((threadIdx.x & 31) == 0) { atomicAdd(&ssum[k], s); atomicAdd(&ssq[k], q); }
        }
        __syncthreads();
        if (threadIdx.x < NCO)
            atomicAdd(&stats[cog + threadIdx.x], ssum[threadIdx.x]);
        else if (threadIdx.x < 2 * NCO)
            atomicAdd(&stats[CO + cog + threadIdx.x - NCO], ssq[threadIdx.x - NCO]);
    } else {
        float* pb = zout + ((jp0 * 2 + b) * CO) * DO3;
#pragma unroll
        for (int p = 0; p < NP; p++) {
            float2 a = unpack2(aA[p]);
            float2 bb = unpack2(aB[p]);
            pb[(cog + 2 * p)     * DO3 + roA]     = a.x;
            pb[(cog + 2 * p + 1) * DO3 + roA]     = a.y;
            pb[(cog + 2 * p)     * DO3 + roA + 2] = bb.x;
            pb[(cog + 2 * p + 1) * DO3 + roA + 2] = bb.y;
        }
    }
}

// ---------------------------------------------------------------------------
// Post body (sum partials + bias + mask + leaky + padded store + stats)
// ---------------------------------------------------------------------------
template <int NS>
__device__ __forceinline__ void post_body(int blk, const float* __restrict__ pbuf,
                                          const float* __restrict__ bias,
                                          const float* __restrict__ mo, float* __restrict__ z,
                                          float* __restrict__ stats, int CO, int D, int pd) {
    const int D3 = D * D * D;
    int idx = blk * 256 + threadIdx.x;
    int r = idx % D3, c = (idx / D3) % CO, b = idx / (D3 * CO);
    float s = 0.f;
#pragma unroll
    for (int j = 0; j < NS; j++) s += pbuf[((j * 2 + b) * CO + c) * D3 + r];
    float m = mo[b * D3 + r];
    float y = (s + bias[c]) * m;
    y = y >= 0.f ? y : 0.01f * y;
    int P = D + 2 * pd, P3 = P * P * P;
    int rz = r / (D * D), ry = (r / D) % D, rx = r % D;
    z[(b * CO + c) * P3 + ((rz + pd) * P + (ry + pd)) * P + (rx + pd)] = y;
    float ss = y, q = y * y;
    for (int o = 16; o; o >>= 1) {
        ss += __shfl_xor_sync(0xffffffffu, ss, o);
        q  += __shfl_xor_sync(0xffffffffu, q, o);
    }
    if ((threadIdx.x & 31) == 0) { atomicAdd(&stats[c], ss); atomicAdd(&stats[CO + c], q); }
}

template <int NS, int MDI, int MDO>
__global__ void k_post_mf(const float* __restrict__ pbuf, const float* __restrict__ bias,
                          const float* __restrict__ mo, float* __restrict__ z,
                          float* __restrict__ stats, int CO, int D, int pd, int mainBlocks,
                          const float* __restrict__ mi, float* __restrict__ mnext,
                          float* __restrict__ cnt) {
    if ((int)blockIdx.x >= mainBlocks) {
        maskd_fwd_body<MDI, MDO>(blockIdx.x - mainBlocks, mi, mnext, cnt);
        return;
    }
    post_body<NS>(blockIdx.x, pbuf, bias, mo, z, stats, CO, D, pd);
}

template <int NS, int MDI, int MDO>
__global__ void k_post_mt(const float* __restrict__ pbuf, const float* __restrict__ bias,
                          const float* __restrict__ mo, float* __restrict__ z,
                          float* __restrict__ stats, int CO, int D, int pd, int mainBlocks,
                          const float* __restrict__ mi, float* __restrict__ mnext,
                          float* __restrict__ cnt) {
    if ((int)blockIdx.x >= mainBlocks) {
        maskd_t_body<MDI, MDO>(blockIdx.x - mainBlocks, mi, mnext, cnt);
        return;
    }
    post_body<NS>(blockIdx.x, pbuf, bias, mo, z, stats, CO, D, pd);
}

// ---------------------------------------------------------------------------
// BN apply with inline finalize (+ optional fused fwd-dilation blocks)
// ---------------------------------------------------------------------------
__device__ __forceinline__ void norm_body(int blk, float* __restrict__ z,
                                          const float* __restrict__ mo,
                                          const float* __restrict__ stats,
                                          const float* __restrict__ g,
                                          const float* __restrict__ be,
                                          int CO, int D, int pd) {
    __shared__ float sc[128], sh[128];
    if (threadIdx.x < CO) {
        int c = threadIdx.x;
        float cnt  = fmaxf(stats[2 * CO], 1.f);
        float mean = stats[c] / cnt;
        float var  = stats[CO + c] / cnt - mean * mean;
        float s = g[c] * rsqrtf(var + 1e-5f);
        sc[c] = s;
        sh[c] = be[c] - mean * s;
    }
    __syncthreads();
    const int D3 = D * D * D, P = D + 2 * pd, P3 = P * P * P;
    int idx = blk * 256 + threadIdx.x;
    int c = (idx / D3) % CO, b = idx / (D3 * CO), r = idx % D3;
    int rz = r / (D * D), ry = (r / D) % D, rx = r % D;
    int off = (b * CO + c) * P3 + ((rz + pd) * P + (ry + pd)) * P + (rx + pd);
    z[off] = fmaf(z[off], sc[c], sh[c]) * mo[b * D3 + r];
}

__global__ void k_norm(float* __restrict__ z, const float* __restrict__ mo,
                       const float* __restrict__ stats, const float* __restrict__ g,
                       const float* __restrict__ be, int CO, int D, int pd) {
    norm_body(blockIdx.x, z, mo, stats, g, be, CO, D, pd);
}

template <int MDI, int MDO>
__global__ void k_norm_mf(float* __restrict__ z, const float* __restrict__ mo,
                          const float* __restrict__ stats, const float* __restrict__ g,
                          const float* __restrict__ be, int CO, int D, int pd,
                          int mainBlocks, const float* __restrict__ mi,
                          float* __restrict__ mnext, float* __restrict__ cnt) {
    if ((int)blockIdx.x >= mainBlocks) {
        maskd_fwd_body<MDI, MDO>(blockIdx.x - mainBlocks, mi, mnext, cnt);
        return;
    }
    norm_body(blockIdx.x, z, mo, stats, g, be, CO, D, pd);
}

// ---------------------------------------------------------------------------
// Head fused with BN-5: out = m * sum_ci fw[ci]*(z*sc[ci]+sh[ci]) + fb
// ---------------------------------------------------------------------------
__global__ void __launch_bounds__(256) k_head(const float* __restrict__ x,
                                              const float* __restrict__ fwT,
                                              const float* __restrict__ fb,
                                              const float* __restrict__ stats,
                                              const float* __restrict__ g,
                                              const float* __restrict__ be,
                                              const float* __restrict__ mo,
                                              float* __restrict__ out) {
    __shared__ __align__(16) float sw[64 * 32];
    __shared__ float sc[64], sh[64];
    for (int i = threadIdx.x; i < 2048; i += 256) sw[i] = fwT[i];
    if (threadIdx.x < 64) {
        int c = threadIdx.x;
        float cnt  = fmaxf(stats[128], 1.f);
        float mean = stats[c] / cnt;
        float var  = stats[64 + c] / cnt - mean * mean;
        float s = g[c] * rsqrtf(var + 1e-5f);
        sc[c] = s;
        sh[c] = be[c] - mean * s;
    }
    __syncthreads();
    const int D3 = 32768;
    int v = blockIdx.x * 256 + threadIdx.x;
    int b = v / D3, r = v % D3;
    const float m = mo[v];
    u64 acc2[16];
#pragma unroll
    for (int k = 0; k < 16; k++) acc2[k] = 0ull;
    const float* xp = x + b * 64 * D3 + r;
#pragma unroll 8
    for (int ci = 0; ci < 64; ci++) {
        float zn = fmaf(*xp, sc[ci], sh[ci]); xp += D3;
        u64 xv = pack2(zn);
        const ulonglong2* w2 = reinterpret_cast<const ulonglong2*>(sw + ci * 32);
#pragma unroll
        for (int q = 0; q < 8; q++) {
            ulonglong2 w = w2[q];
            acc2[2 * q]     = ffma2(xv, w.x, acc2[2 * q]);
            acc2[2 * q + 1] = ffma2(xv, w.y, acc2[2 * q + 1]);
        }
    }
#pragma unroll
    for (int k = 0; k < 16; k++) {
        float2 a = unpack2(acc2[k]);
        out[(b * 32 + 2 * k)     * D3 + r] = fmaf(a.x, m, fb[2 * k]);
        out[(b * 32 + 2 * k + 1) * D3 + r] = fmaf(a.y, m, fb[2 * k + 1]);
    }
}

// ---------------------------------------------------------------------------
// Host launcher
// ---------------------------------------------------------------------------
extern "C" void kernel_launch(void* const* d_in, const int* in_sizes, int n_in,
                              void* d_out, int out_size) {
    (void)in_sizes; (void)n_in; (void)out_size;
    float* S = nullptr;
    cudaGetSymbolAddress((void**)&S, g_scratch);

    const float* feat = (const float*)d_in[0];
    const float* mask = (const float*)d_in[1];
    const float* w1  = (const float*)d_in[2];  const float* b1  = (const float*)d_in[3];
    const float* g1  = (const float*)d_in[4];  const float* be1 = (const float*)d_in[5];
    const float* w2  = (const float*)d_in[6];  const float* b2  = (const float*)d_in[7];
    const float* g2  = (const float*)d_in[8];  const float* be2 = (const float*)d_in[9];
    const float* w3  = (const float*)d_in[10]; const float* b3  = (const float*)d_in[11];
    const float* g3  = (const float*)d_in[12]; const float* be3 = (const float*)d_in[13];
    const float* tw1 = (const float*)d_in[14]; const float* tb1 = (const float*)d_in[15];
    const float* tg1 = (const float*)d_in[16]; const float* tbe1= (const float*)d_in[17];
    const float* tw2 = (const float*)d_in[18]; const float* tb2 = (const float*)d_in[19];
    const float* tg2 = (const float*)d_in[20]; const float* tbe2= (const float*)d_in[21];
    const float* fw  = (const float*)d_in[22]; const float* fb  = (const float*)d_in[23];
    float* out = (float*)d_out;

    float *x0 = S+OX0, *z1 = S+OZ1, *z2 = S+OZ2, *z3 = S+OZ3, *z4 = S+OZ4, *z5 = S+OZ5;
    float *m0p = S+OM0P, *m1 = S+OM1, *m2 = S+OM2, *m3 = S+OM3, *m4 = S+OM4, *m5 = S+OM5;
    float *w1T = S+OW1, *w2T = S+OW2, *w3T = S+OW3, *tw1T = S+OTW1, *tw2T = S+OTW2, *fwT = S+OFW;
    float *st = S+OST, *pb = S+OPB;

    k_trans_all<<<8744, 256>>>(w1, w2, w3, tw1, tw2, fw, S);
    k_pre<<<2048, 256>>>(feat, mask, x0, m0p);
    k_maskd64p<<<128, 256>>>(m0p, m1, st + 0 * 260 + 64);

    // stage 1: 4 -> 32, 64^3 -> 32^3, 4vox x 4co, 512 CTAs
    k_conv_fwd2<4, 32, 64, 32, 1, true, 4><<<dim3(64, 8), 256>>>(x0, w1T, b1, m1, z1, st + 0 * 260);
    k_norm_mf<32, 16><<<8192 + 32, 256>>>(z1, m1, st + 0 * 260, g1, be1, 32, 32, 1,
                                          8192, m1, m2, st + 1 * 260 + 128);

    // stage 2: 32 -> 64, 32^3 -> 16^3, tz-split x4, 4vox x 4co, 512 CTAs
    k_conv_fwd2<32, 64, 32, 16, 4, false, 4><<<dim3(8, 16, 4), 256>>>(z1, w2T, b2, m2, pb, st + 1 * 260);
    k_post_mf<4, 16, 8><<<2048 + 4, 256>>>(pb, b2, m2, z2, st + 1 * 260, 64, 16, 1,
                                           2048, m2, m3, st + 2 * 260 + 256);
    k_norm<<<2048, 256>>>(z2, m2, st + 1 * 260, g2, be2, 64, 16, 1);

    // stage 3: 64 -> 128, 16^3 -> 8^3, (tz,ty)-split x16, 4vox x 4co, 512 CTAs
    k_conv_fwd2<64, 128, 16, 8, 16, false, 4><<<dim3(1, 32, 16), 256>>>(z2, w3T, b3, m3, pb, st + 2 * 260);
    k_post_mt<16, 8, 16><<<512 + 32, 256>>>(pb, b3, m3, z3, st + 2 * 260, 128, 8, 1,
                                            512, m3, m4, st + 3 * 260 + 256);
    k_norm<<<512, 256>>>(z3, m3, st + 2 * 260, g3, be3, 128, 8, 1);

    // stage 4: tconv 128 -> 128, 8^3 -> 16^3, jp-split x4, 2vox x 8co, 1024 CTAs
    k_conv_t2<128, 128, 8, true, 4, 8><<<dim3(2, 16, 32), 256>>>(z3, tw1T, tb1, m4, pb, st + 3 * 260);
    k_post_mt<4, 16, 32><<<4096 + 256, 256>>>(pb, tb1, m4, z4, st + 3 * 260, 128, 16, 1,
                                              4096, m4, m5, st + 4 * 260 + 128);
    k_norm<<<4096, 256>>>(z4, m4, st + 3 * 260, tg1, tbe1, 128, 16, 1);

    // stage 5: tconv 128 -> 64, 16^3 -> 32^3, unsplit, 2vox x 8co, 1024 CTAs
    k_conv_t2<128, 64, 16, false, 1, 8><<<dim3(16, 8, 8), 256>>>(z4, tw2T, tb2, m5, z5, st + 4 * 260);

    // head with fused BN-5
    k_head<<<256, 256>>>(z5, fwT, fb, st + 4 * 260, tg2, tbe2, m5, out);
}

// round 16
// speedup vs baseline: 1.1552x; 1.1552x over previous
#include <cuda_runtime.h>
#include <math.h>

typedef unsigned long long u64;

__device__ __forceinline__ u64 pack2(float v) {
    u64 r; asm("mov.b64 %0, {%1, %1};" : "=l"(r) : "f"(v)); return r;
}
__device__ __forceinline__ u64 ffma2(u64 a, u64 b, u64 c) {
    u64 d; asm("fma.rn.f32x2 %0, %1, %2, %3;" : "=l"(d) : "l"(a), "l"(b), "l"(c)); return d;
}
__device__ __forceinline__ float2 unpack2(u64 a) {
    float2 f; asm("mov.b64 {%0, %1}, %2;" : "=f"(f.x), "=f"(f.y) : "l"(a)); return f;
}

// ---------------------------------------------------------------------------
// Scratch arena. Activations halo-padded: dim D stored as P=D+2, interior
// voxel (z,y,x) at ((z+1)*P+(y+1))*P+(x+1). Halos are NEVER written -> stay 0.
// ---------------------------------------------------------------------------
constexpr int OX0  = 0;
constexpr int OZ1  = 2299968;
constexpr int OZ2  = 4815424;
constexpr int OZ3  = 5561920;
constexpr int OZ4  = 5817920;
constexpr int OZ5  = 7310912;
constexpr int OM0P = 11505216;
constexpr int OM1  = 12080208;
constexpr int OM2  = 12145744;
constexpr int OM3  = 12153936;
constexpr int OM4  = 12154960;
constexpr int OM5  = 12163152;
constexpr int OW1  = 12228688;
constexpr int OW2  = 12236880;
constexpr int OW3  = 12367952;
constexpr int OTW1 = 12892240;
constexpr int OTW2 = 13940816;
constexpr int OFW  = 14465104;
constexpr int OST  = 14467152;
constexpr int OPB  = 14468452;
constexpr int TOT_SCRATCH = 22857216;

__device__ __align__(16) float g_scratch[TOT_SCRATCH];

// weight transposes + stats zeroing
__global__ void k_trans_all(const float* __restrict__ w1, const float* __restrict__ w2,
                            const float* __restrict__ w3, const float* __restrict__ tw1,
                            const float* __restrict__ tw2, const float* __restrict__ fw,
                            float* __restrict__ S) {
    int idx = blockIdx.x * 256 + threadIdx.x;
    if (idx < 5 * 260) S[OST + idx] = 0.f;
    const float* src; float* dst; int CI, CO, i = idx;
    if (i < 8192)            { src = w1;  dst = S + OW1;  CI = 4;   CO = 32;  }
    else if ((i -= 8192)  < 131072)  { src = w2;  dst = S + OW2;  CI = 32;  CO = 64;  }
    else if ((i -= 131072) < 524288) { src = w3;  dst = S + OW3;  CI = 64;  CO = 128; }
    else if ((i -= 524288) < 1048576){ src = tw1; dst = S + OTW1; CI = 128; CO = 128; }
    else if ((i -= 1048576)< 524288) { src = tw2; dst = S + OTW2; CI = 128; CO = 64;  }
    else if ((i -= 524288) < 2048)   { S[OFW + (i % 64) * 32 + i / 64] = fw[i]; return; }
    else return;
    int t = i & 63, ci = (i >> 6) % CI, co = i / (64 * CI);
    dst[(t * CI + ci) * CO + co] = src[i];
}

// masked input into padded x0 + padded m0p
__global__ void k_pre(const float* __restrict__ feat, const float* __restrict__ mask,
                      float* __restrict__ x0, float* __restrict__ m0p) {
    int v = blockIdx.x * 256 + threadIdx.x;
    float m = mask[v] > 0.5f ? 1.f : 0.f;
    int b = v >> 18, r = v & 262143;
    int z = r >> 12, y = (r >> 6) & 63, x = r & 63;
    int poff = ((z + 1) * 66 + (y + 1)) * 66 + (x + 1);
    m0p[b * 287496 + poff] = m;
#pragma unroll
    for (int c = 0; c < 4; c++)
        x0[(b * 4 + c) * 287496 + poff] = feat[(b * 4 + c) * 262144 + r] * m;
}

// mask dilation 64^3->32^3 from PADDED m0p, branch-free, 2 voxels/thread
__global__ void k_maskd64p(const float* __restrict__ m0p, float* __restrict__ mo,
                           float* __restrict__ cnt) {
    int v = blockIdx.x * 256 + threadIdx.x;
    int b = v / 16384, rp = v % 16384;
    int r = 2 * rp;
    int oz = r >> 10, oy = (r >> 5) & 31, ox = r & 31;
    const float* base = m0p + b * 287496 + (2 * oz) * 4356 + (2 * oy) * 66 + 2 * ox;
    float sA = 0.f, sB = 0.f;
#pragma unroll
    for (int tz = 0; tz < 4; tz++)
#pragma unroll
        for (int ty = 0; ty < 4; ty++) {
            const float* p = base + tz * 4356 + ty * 66;
            float w0 = __ldg(p), w1 = __ldg(p + 1), w2 = __ldg(p + 2);
            float w3 = __ldg(p + 3), w4 = __ldg(p + 4), w5 = __ldg(p + 5);
            float c = w2 + w3;
            sA += w0 + w1 + c;
            sB += c + w4 + w5;
        }
    float aA = sA > 0.f ? 1.f : 0.f, aB = sB > 0.f ? 1.f : 0.f;
    mo[b * 32768 + r] = aA;
    mo[b * 32768 + r + 1] = aB;
    float s = aA + aB;
    for (int o = 16; o; o >>= 1) s += __shfl_xor_sync(0xffffffffu, s, o);
    if ((threadIdx.x & 31) == 0) atomicAdd(cnt, s);
}

// ---------------------------------------------------------------------------
// Mask dilation device bodies (used by fused kernels' extra blocks)
// ---------------------------------------------------------------------------
template <int DI, int DO>
__device__ __forceinline__ void maskd_fwd_body(int blk, const float* __restrict__ mi,
                                               float* __restrict__ mo, float* __restrict__ cnt) {
    const int DO3 = DO * DO * DO, DI2 = DI * DI, DI3 = DI * DI * DI;
    int v = blk * 256 + threadIdx.x;
    int b = v / DO3, r = v % DO3;
    int oz = r / (DO * DO), oy = (r / DO) % DO, ox = r % DO;
    float m = 0.f;
    for (int tz = 0; tz < 4; tz++) {
        int iz = 2 * oz - 1 + tz;
        if ((unsigned)iz >= DI) continue;
        for (int ty = 0; ty < 4; ty++) {
            int iy = 2 * oy - 1 + ty;
            if ((unsigned)iy >= DI) continue;
            const float* p = mi + b * DI3 + iz * DI2 + iy * DI;
            for (int tx = 0; tx < 4; tx++) {
                int ix = 2 * ox - 1 + tx;
                if ((unsigned)ix < DI) m += p[ix];
            }
        }
    }
    float act = m > 0.f ? 1.f : 0.f;
    mo[v] = act;
    float s = act;
    for (int o = 16; o; o >>= 1) s += __shfl_xor_sync(0xffffffffu, s, o);
    if ((threadIdx.x & 31) == 0) atomicAdd(cnt, s);
}

template <int DI, int DO>
__device__ __forceinline__ void maskd_t_body(int blk, const float* __restrict__ mi,
                                             float* __restrict__ mo, float* __restrict__ cnt) {
    const int DO3 = DO * DO * DO, DI2 = DI * DI, DI3 = DI * DI * DI;
    int v = blk * 256 + threadIdx.x;
    int b = v / DO3, r = v % DO3;
    int oz = r / (DO * DO), oy = (r / DO) % DO, ox = r % DO;
    int izl[2], iyl[2], ixl[2];
    izl[0] = oz >> 1; izl[1] = (oz & 1) ? (oz >> 1) + 1 : (oz >> 1) - 1;
    iyl[0] = oy >> 1; iyl[1] = (oy & 1) ? (oy >> 1) + 1 : (oy >> 1) - 1;
    ixl[0] = ox >> 1; ixl[1] = (ox & 1) ? (ox >> 1) + 1 : (ox >> 1) - 1;
    float m = 0.f;
#pragma unroll
    for (int jz = 0; jz < 2; jz++) {
        int iz = izl[jz];
        if ((unsigned)iz >= DI) continue;
#pragma unroll
        for (int jy = 0; jy < 2; jy++) {
            int iy = iyl[jy];
            if ((unsigned)iy >= DI) continue;
#pragma unroll
            for (int jx = 0; jx < 2; jx++) {
                int ix = ixl[jx];
                if ((unsigned)ix < DI) m += mi[b * DI3 + iz * DI2 + iy * DI + ix];
            }
        }
    }
    float act = m > 0.f ? 1.f : 0.f;
    mo[v] = act;
    float s = act;
    for (int o = 16; o; o >>= 1) s += __shfl_xor_sync(0xffffffffu, s, o);
    if ((threadIdx.x & 31) == 0) atomicAdd(cnt, s);
}

// ---------------------------------------------------------------------------
// Forward conv, 4 adjacent output voxels x 8 co per thread.
// FULLW (for small CI): stage all 64 taps once, zero in-loop syncs.
// SPLIT=1: full conv + epilogue. SPLIT=4: tz-split. SPLIT=16: (tz,ty)-split.
// ---------------------------------------------------------------------------
template <int CI, int CO, int DI, int DO, int SPLIT, bool FULLW>
__global__ void __launch_bounds__(256) k_conv_fwd2(
    const float* __restrict__ x, const float* __restrict__ wT,
    const float* __restrict__ bias, const float* __restrict__ mo,
    float* __restrict__ zout, float* __restrict__ stats) {
    constexpr int PI = DI + 2, PO = DO + 2;
    constexpr int PI2 = PI * PI, PI3 = PI2 * PI, PO3 = PO * PO * PO;
    constexpr int DO3 = DO * DO * DO, QDO3 = DO3 / 4;
    constexpr int NTAP = FULLW ? 64 : ((SPLIT == 16) ? 4 : 16);
    __shared__ __align__(16) float sw[NTAP * CI * 8];
    const int co0 = blockIdx.y * 8;
    const int v = blockIdx.x * 256 + threadIdx.x;
    const int b = v / QDO3, rp = v % QDO3;
    const int r = 4 * rp;
    const int oz = r / (DO * DO), oy = (r / DO) % DO, ox = r % DO;
    u64 acc[4][4];
#pragma unroll
    for (int vv = 0; vv < 4; vv++)
#pragma unroll
        for (int p = 0; p < 4; p++) acc[vv][p] = 0ull;
    const float* xbase = x + (b * CI) * PI3 + (2 * oz) * PI2 + (2 * oy) * PI + 2 * ox;

    auto stage = [&](int t0, int ntap) {
        for (int i = threadIdx.x; i < ntap * CI * 8; i += 256) {
            int k = i & 7, ci = (i >> 3) % CI, s = i / (8 * CI);
            sw[i] = wT[((t0 + s) * CI + ci) * CO + co0 + k];
        }
    };
    auto body = [&](int tz, int ty, const float* swrow) {
        const float* xr = xbase + tz * PI2 + ty * PI;
#pragma unroll 4
        for (int ci = 0; ci < CI; ci++) {
            const float* xp = xr + ci * PI3;
            float2 q0 = *reinterpret_cast<const float2*>(xp);
            float2 q1 = *reinterpret_cast<const float2*>(xp + 2);
            float2 q2 = *reinterpret_cast<const float2*>(xp + 4);
            float2 q3 = *reinterpret_cast<const float2*>(xp + 6);
            float2 q4 = *reinterpret_cast<const float2*>(xp + 8);
            u64 p[10];
            p[0] = pack2(q0.x); p[1] = pack2(q0.y); p[2] = pack2(q1.x);
            p[3] = pack2(q1.y); p[4] = pack2(q2.x); p[5] = pack2(q2.y);
            p[6] = pack2(q3.x); p[7] = pack2(q3.y); p[8] = pack2(q4.x);
            p[9] = pack2(q4.y);
#pragma unroll
            for (int tx = 0; tx < 4; tx++) {
                const float* wp = swrow + (tx * CI + ci) * 8;
                ulonglong2 w0 = *reinterpret_cast<const ulonglong2*>(wp);
                ulonglong2 w1 = *reinterpret_cast<const ulonglong2*>(wp + 4);
#pragma unroll
                for (int vv = 0; vv < 4; vv++) {
                    acc[vv][0] = ffma2(p[2 * vv + tx], w0.x, acc[vv][0]);
                    acc[vv][1] = ffma2(p[2 * vv + tx], w0.y, acc[vv][1]);
                    acc[vv][2] = ffma2(p[2 * vv + tx], w1.x, acc[vv][2]);
                    acc[vv][3] = ffma2(p[2 * vv + tx], w1.y, acc[vv][3]);
                }
            }
        }
    };

    if constexpr (SPLIT == 1) {
        if constexpr (FULLW) {
            stage(0, 64);
            __syncthreads();
            for (int tz = 0; tz < 4; tz++)
                for (int ty = 0; ty < 4; ty++)
                    body(tz, ty, sw + (tz * 16 + ty * 4) * CI * 8);
        } else {
            for (int tz = 0; tz < 4; tz++) {
                __syncthreads();
                stage(tz * 16, 16);
                __syncthreads();
                for (int ty = 0; ty < 4; ty++) body(tz, ty, sw + (ty * 4) * CI * 8);
            }
        }
    } else if constexpr (SPLIT == 4) {
        const int tz = blockIdx.z;
        stage(tz * 16, 16);
        __syncthreads();
        for (int ty = 0; ty < 4; ty++) body(tz, ty, sw + (ty * 4) * CI * 8);
    } else {
        const int tz = blockIdx.z >> 2, ty = blockIdx.z & 3;
        stage(tz * 16 + ty * 4, 4);
        __syncthreads();
        body(tz, ty, sw);
    }

    if constexpr (SPLIT == 1) {
        __shared__ float ssum[8], ssq[8];
        float mk[4];
#pragma unroll
        for (int vv = 0; vv < 4; vv++) mk[vv] = mo[b * DO3 + r + vv];
        const int poffA = ((oz + 1) * PO + (oy + 1)) * PO + (ox + 1);
        float s8[8], q8[8];
#pragma unroll
        for (int p = 0; p < 4; p++) {
            float bi0 = bias[co0 + 2 * p], bi1 = bias[co0 + 2 * p + 1];
            float y0[4], y1[4];
#pragma unroll
            for (int vv = 0; vv < 4; vv++) {
                float2 a = unpack2(acc[vv][p]);
                float t0 = (a.x + bi0) * mk[vv];
                float t1 = (a.y + bi1) * mk[vv];
                y0[vv] = t0 >= 0.f ? t0 : 0.01f * t0;
                y1[vv] = t1 >= 0.f ? t1 : 0.01f * t1;
            }
            float* zp0 = zout + (b * CO + co0 + 2 * p) * PO3 + poffA;
            float* zp1 = zp0 + PO3;
#pragma unroll
            for (int vv = 0; vv < 4; vv++) { zp0[vv] = y0[vv]; zp1[vv] = y1[vv]; }
            s8[2*p]   = y0[0] + y0[1] + y0[2] + y0[3];
            q8[2*p]   = y0[0]*y0[0] + y0[1]*y0[1] + y0[2]*y0[2] + y0[3]*y0[3];
            s8[2*p+1] = y1[0] + y1[1] + y1[2] + y1[3];
            q8[2*p+1] = y1[0]*y1[0] + y1[1]*y1[1] + y1[2]*y1[2] + y1[3]*y1[3];
        }
        __syncthreads();
        if (threadIdx.x < 8) { ssum[threadIdx.x] = 0.f; ssq[threadIdx.x] = 0.f; }
        __syncthreads();
#pragma unroll
        for (int k = 0; k < 8; k++) {
            float s = s8[k], q = q8[k];
            for (int o = 16; o; o >>= 1) {
                s += __shfl_xor_sync(0xffffffffu, s, o);
                q += __shfl_xor_sync(0xffffffffu, q, o);
            }
            if ((threadIdx.x & 31) == 0) { atomicAdd(&ssum[k], s); atomicAdd(&ssq[k], q); }
        }
        __syncthreads();
        if (threadIdx.x < 8)
            atomicAdd(&stats[co0 + threadIdx.x], ssum[threadIdx.x]);
        else if (threadIdx.x < 16)
            atomicAdd(&stats[CO + co0 + threadIdx.x - 8], ssq[threadIdx.x - 8]);
    } else {
        float* pb = zout + ((blockIdx.z * 2 + b) * CO) * DO3 + r;
#pragma unroll
        for (int p = 0; p < 4; p++) {
            float2 a0 = unpack2(acc[0][p]);
            float2 a1 = unpack2(acc[1][p]);
            float2 a2 = unpack2(acc[2][p]);
            float2 a3 = unpack2(acc[3][p]);
            *reinterpret_cast<float4*>(pb + (co0 + 2 * p) * DO3)
                = make_float4(a0.x, a1.x, a2.x, a3.x);
            *reinterpret_cast<float4*>(pb + (co0 + 2 * p + 1) * DO3)
                = make_float4(a0.y, a1.y, a2.y, a3.y);
        }
    }
}

// ---------------------------------------------------------------------------
// Transpose conv, 2 adjacent input voxels x 16 co per thread, parity classes.
// ---------------------------------------------------------------------------
template <int CI, int CO, int DI, bool PADOUT, int SLOTS>
__global__ void __launch_bounds__(256) k_conv_t2(
    const float* __restrict__ x, const float* __restrict__ wT,
    const float* __restrict__ bias, const float* __restrict__ mo,
    float* __restrict__ zout, float* __restrict__ stats) {
    constexpr int DO = 2 * DI, PI = DI + 2, PO = DO + 2;
    constexpr int PI2 = PI * PI, PI3 = PI2 * PI;
    constexpr int DI2 = DI * DI, DI3 = DI2 * DI, DO3 = DO * DO * DO;
    constexpr int PO3 = PO * PO * PO, HDI3 = DI3 / 2;
    constexpr int NJP = 4 / SLOTS;
    __shared__ __align__(16) float sw[2 * CI * 16];
    const int cls = (SLOTS == 1) ? blockIdx.z : (blockIdx.z & 7);
    const int jp0 = (SLOTS == 1) ? 0 : (blockIdx.z >> 3);
    const int pz = (cls >> 2) & 1, py = (cls >> 1) & 1, px = cls & 1;
    const int cog = blockIdx.y * 16;
    const int v = blockIdx.x * 256 + threadIdx.x;
    const int b = v / HDI3, rp = v % HDI3;
    const int r = 2 * rp;
    const int zi = r / DI2, yi = (r / DI) % DI, xi = r % DI;

    u64 aA[8], aB[8];
#pragma unroll
    for (int k = 0; k < 8; k++) { aA[k] = 0ull; aB[k] = 0ull; }

    const int sxp = (px ? xi : xi - 1) + 1;

    for (int jj = 0; jj < NJP; jj++) {
        const int jp = jp0 * NJP + jj;
        const int jz = jp >> 1, jy = jp & 1;
        const int tz = pz ? 2 - 2 * jz : 1 + 2 * jz;
        const int ty = py ? 2 - 2 * jy : 1 + 2 * jy;
        if (jj) __syncthreads();
        for (int i = threadIdx.x; i < 2 * CI * 16; i += 256) {
            int k = i & 15, ci = (i >> 4) % CI, jx = i / (16 * CI);
            int tx = px ? 2 - 2 * jx : 1 + 2 * jx;
            sw[i] = wT[((tz * 16 + ty * 4 + tx) * CI + ci) * CO + cog + k];
        }
        __syncthreads();
        const int iz = pz ? zi + jz : zi - jz;
        const int iy = py ? yi + jy : yi - jy;
        const float* xr = x + (b * CI) * PI3 + (iz + 1) * PI2 + (iy + 1) * PI + sxp;
#pragma unroll 4
        for (int ci = 0; ci < CI; ci++) {
            const float* xp = xr + ci * PI3;
            u64 p0 = pack2(xp[0]), p1 = pack2(xp[1]), p2 = pack2(xp[2]);
            {
                const float* wp = sw + ci * 16;
                ulonglong2 w0 = *reinterpret_cast<const ulonglong2*>(wp);
                ulonglong2 w1 = *reinterpret_cast<const ulonglong2*>(wp + 4);
                ulonglong2 w2 = *reinterpret_cast<const ulonglong2*>(wp + 8);
                ulonglong2 w3 = *reinterpret_cast<const ulonglong2*>(wp + 12);
                u64 xA = px ? p0 : p1;
                u64 xB = px ? p1 : p2;
                aA[0] = ffma2(xA, w0.x, aA[0]); aA[1] = ffma2(xA, w0.y, aA[1]);
                aA[2] = ffma2(xA, w1.x, aA[2]); aA[3] = ffma2(xA, w1.y, aA[3]);
                aA[4] = ffma2(xA, w2.x, aA[4]); aA[5] = ffma2(xA, w2.y, aA[5]);
                aA[6] = ffma2(xA, w3.x, aA[6]); aA[7] = ffma2(xA, w3.y, aA[7]);
                aB[0] = ffma2(xB, w0.x, aB[0]); aB[1] = ffma2(xB, w0.y, aB[1]);
                aB[2] = ffma2(xB, w1.x, aB[2]); aB[3] = ffma2(xB, w1.y, aB[3]);
                aB[4] = ffma2(xB, w2.x, aB[4]); aB[5] = ffma2(xB, w2.y, aB[5]);
                aB[6] = ffma2(xB, w3.x, aB[6]); aB[7] = ffma2(xB, w3.y, aB[7]);
            }
            {
                const float* wp = sw + (CI + ci) * 16;
                ulonglong2 w0 = *reinterpret_cast<const ulonglong2*>(wp);
                ulonglong2 w1 = *reinterpret_cast<const ulonglong2*>(wp + 4);
                ulonglong2 w2 = *reinterpret_cast<const ulonglong2*>(wp + 8);
                ulonglong2 w3 = *reinterpret_cast<const ulonglong2*>(wp + 12);
                u64 xA = px ? p1 : p0;
                u64 xB = px ? p2 : p1;
                aA[0] = ffma2(xA, w0.x, aA[0]); aA[1] = ffma2(xA, w0.y, aA[1]);
                aA[2] = ffma2(xA, w1.x, aA[2]); aA[3] = ffma2(xA, w1.y, aA[3]);
                aA[4] = ffma2(xA, w2.x, aA[4]); aA[5] = ffma2(xA, w2.y, aA[5]);
                aA[6] = ffma2(xA, w3.x, aA[6]); aA[7] = ffma2(xA, w3.y, aA[7]);
                aB[0] = ffma2(xB, w0.x, aB[0]); aB[1] = ffma2(xB, w0.y, aB[1]);
                aB[2] = ffma2(xB, w1.x, aB[2]); aB[3] = ffma2(xB, w1.y, aB[3]);
                aB[4] = ffma2(xB, w2.x, aB[4]); aB[5] = ffma2(xB, w2.y, aB[5]);
                aB[6] = ffma2(xB, w3.x, aB[6]); aB[7] = ffma2(xB, w3.y, aB[7]);
            }
        }
    }

    const int oz = 2 * zi + pz, oy = 2 * yi + py;
    const int oxA = 2 * xi + px;
    const int roA = (oz * DO + oy) * DO + oxA;

    if constexpr (SLOTS == 1) {
        __shared__ float ssum[16], ssq[16];
        const float mA = mo[b * DO3 + roA], mB = mo[b * DO3 + roA + 2];
        const int ooffA = PADOUT ? ((oz + 1) * PO + (oy + 1)) * PO + (oxA + 1) : roA;
        const int ostr  = PADOUT ? PO3 : DO3;
        float zsA[16], zsB[16];
#pragma unroll
        for (int p = 0; p < 8; p++) {
            float2 a = unpack2(aA[p]);
            float2 bb = unpack2(aB[p]);
            float bi0 = bias[cog + 2 * p], bi1 = bias[cog + 2 * p + 1];
            float yA0 = (a.x + bi0) * mA, yA1 = (a.y + bi1) * mA;
            float yB0 = (bb.x + bi0) * mB, yB1 = (bb.y + bi1) * mB;
            zsA[2*p]   = yA0 >= 0.f ? yA0 : 0.01f * yA0;
            zsA[2*p+1] = yA1 >= 0.f ? yA1 : 0.01f * yA1;
            zsB[2*p]   = yB0 >= 0.f ? yB0 : 0.01f * yB0;
            zsB[2*p+1] = yB1 >= 0.f ? yB1 : 0.01f * yB1;
            float* zp0 = zout + (b * CO + cog + 2 * p) * ostr + ooffA;
            float* zp1 = zout + (b * CO + cog + 2 * p + 1) * ostr + ooffA;
            zp0[0] = zsA[2*p];   zp0[2] = zsB[2*p];
            zp1[0] = zsA[2*p+1]; zp1[2] = zsB[2*p+1];
        }
        __syncthreads();
        if (threadIdx.x < 16) { ssum[threadIdx.x] = 0.f; ssq[threadIdx.x] = 0.f; }
        __syncthreads();
#pragma unroll
        for (int k = 0; k < 16; k++) {
            float s = zsA[k] + zsB[k];
            float q = zsA[k] * zsA[k] + zsB[k] * zsB[k];
            for (int o = 16; o; o >>= 1) {
                s += __shfl_xor_sync(0xffffffffu, s, o);
                q += __shfl_xor_sync(0xffffffffu, q, o);
            }
            if ((threadIdx.x & 31) == 0) { atomicAdd(&ssum[k], s); atomicAdd(&ssq[k], q); }
        }
        __syncthreads();
        if (threadIdx.x < 16)
            atomicAdd(&stats[cog + threadIdx.x], ssum[threadIdx.x]);
        else if (threadIdx.x < 32)
            atomicAdd(&stats[CO + cog + threadIdx.x - 16], ssq[threadIdx.x - 16]);
    } else {
        float* pb = zout + ((jp0 * 2 + b) * CO) * DO3;
#pragma unroll
        for (int p = 0; p < 8; p++) {
            float2 a = unpack2(aA[p]);
            float2 bb = unpack2(aB[p]);
            pb[(cog + 2 * p)     * DO3 + roA]     = a.x;
            pb[(cog + 2 * p + 1) * DO3 + roA]     = a.y;
            pb[(cog + 2 * p)     * DO3 + roA + 2] = bb.x;
            pb[(cog + 2 * p + 1) * DO3 + roA + 2] = bb.y;
        }
    }
}

// ---------------------------------------------------------------------------
// Post body (sum partials + bias + mask + leaky + padded store + stats)
// ---------------------------------------------------------------------------
template <int NS>
__device__ __forceinline__ void post_body(int blk, const float* __restrict__ pbuf,
                                          const float* __restrict__ bias,
                                          const float* __restrict__ mo, float* __restrict__ z,
                                          float* __restrict__ stats, int CO, int D, int pd) {
    const int D3 = D * D * D;
    int idx = blk * 256 + threadIdx.x;
    int r = idx % D3, c = (idx / D3) % CO, b = idx / (D3 * CO);
    float s = 0.f;
#pragma unroll
    for (int j = 0; j < NS; j++) s += pbuf[((j * 2 + b) * CO + c) * D3 + r];
    float m = mo[b * D3 + r];
    float y = (s + bias[c]) * m;
    y = y >= 0.f ? y : 0.01f * y;
    int P = D + 2 * pd, P3 = P * P * P;
    int rz = r / (D * D), ry = (r / D) % D, rx = r % D;
    z[(b * CO + c) * P3 + ((rz + pd) * P + (ry + pd)) * P + (rx + pd)] = y;
    float ss = y, q = y * y;
    for (int o = 16; o; o >>= 1) {
        ss += __shfl_xor_sync(0xffffffffu, ss, o);
        q  += __shfl_xor_sync(0xffffffffu, q, o);
    }
    if ((threadIdx.x & 31) == 0) { atomicAdd(&stats[c], ss); atomicAdd(&stats[CO + c], q); }
}

template <int NS, int MDI, int MDO>
__global__ void k_post_mf(const float* __restrict__ pbuf, const float* __restrict__ bias,
                          const float* __restrict__ mo, float* __restrict__ z,
                          float* __restrict__ stats, int CO, int D, int pd, int mainBlocks,
                          const float* __restrict__ mi, float* __restrict__ mnext,
                          float* __restrict__ cnt) {
    if ((int)blockIdx.x >= mainBlocks) {
        maskd_fwd_body<MDI, MDO>(blockIdx.x - mainBlocks, mi, mnext, cnt);
        return;
    }
    post_body<NS>(blockIdx.x, pbuf, bias, mo, z, stats, CO, D, pd);
}

template <int NS, int MDI, int MDO>
__global__ void k_post_mt(const float* __restrict__ pbuf, const float* __restrict__ bias,
                          const float* __restrict__ mo, float* __restrict__ z,
                          float* __restrict__ stats, int CO, int D, int pd, int mainBlocks,
                          const float* __restrict__ mi, float* __restrict__ mnext,
                          float* __restrict__ cnt) {
    if ((int)blockIdx.x >= mainBlocks) {
        maskd_t_body<MDI, MDO>(blockIdx.x - mainBlocks, mi, mnext, cnt);
        return;
    }
    post_body<NS>(blockIdx.x, pbuf, bias, mo, z, stats, CO, D, pd);
}

// ---------------------------------------------------------------------------
// BN apply with inline finalize (+ optional fused fwd-dilation blocks)
// ---------------------------------------------------------------------------
__device__ __forceinline__ void norm_body(int blk, float* __restrict__ z,
                                          const float* __restrict__ mo,
                                          const float* __restrict__ stats,
                                          const float* __restrict__ g,
                                          const float* __restrict__ be,
                                          int CO, int D, int pd) {
    __shared__ float sc[128], sh[128];
    if (threadIdx.x < CO) {
        int c = threadIdx.x;
        float cnt  = fmaxf(stats[2 * CO], 1.f);
        float mean = stats[c] / cnt;
        float var  = stats[CO + c] / cnt - mean * mean;
        float s = g[c] * rsqrtf(var + 1e-5f);
        sc[c] = s;
        sh[c] = be[c] - mean * s;
    }
    __syncthreads();
    const int D3 = D * D * D, P = D + 2 * pd, P3 = P * P * P;
    int idx = blk * 256 + threadIdx.x;
    int c = (idx / D3) % CO, b = idx / (D3 * CO), r = idx % D3;
    int rz = r / (D * D), ry = (r / D) % D, rx = r % D;
    int off = (b * CO + c) * P3 + ((rz + pd) * P + (ry + pd)) * P + (rx + pd);
    z[off] = fmaf(z[off], sc[c], sh[c]) * mo[b * D3 + r];
}

__global__ void k_norm(float* __restrict__ z, const float* __restrict__ mo,
                       const float* __restrict__ stats, const float* __restrict__ g,
                       const float* __restrict__ be, int CO, int D, int pd) {
    norm_body(blockIdx.x, z, mo, stats, g, be, CO, D, pd);
}

template <int MDI, int MDO>
__global__ void k_norm_mf(float* __restrict__ z, const float* __restrict__ mo,
                          const float* __restrict__ stats, const float* __restrict__ g,
                          const float* __restrict__ be, int CO, int D, int pd,
                          int mainBlocks, const float* __restrict__ mi,
                          float* __restrict__ mnext, float* __restrict__ cnt) {
    if ((int)blockIdx.x >= mainBlocks) {
        maskd_fwd_body<MDI, MDO>(blockIdx.x - mainBlocks, mi, mnext, cnt);
        return;
    }
    norm_body(blockIdx.x, z, mo, stats, g, be, CO, D, pd);
}

// ---------------------------------------------------------------------------
// Head fused with BN-5: out = m * sum_ci fw[ci]*(z*sc[ci]+sh[ci]) + fb
// ---------------------------------------------------------------------------
__global__ void __launch_bounds__(256) k_head(const float* __restrict__ x,
                                              const float* __restrict__ fwT,
                                              const float* __restrict__ fb,
                                              const float* __restrict__ stats,
                                              const float* __restrict__ g,
                                              const float* __restrict__ be,
                                              const float* __restrict__ mo,
                                              float* __restrict__ out) {
    __shared__ __align__(16) float sw[64 * 32];
    __shared__ float sc[64], sh[64];
    for (int i = threadIdx.x; i < 2048; i += 256) sw[i] = fwT[i];
    if (threadIdx.x < 64) {
        int c = threadIdx.x;
        float cnt  = fmaxf(stats[128], 1.f);
        float mean = stats[c] / cnt;
        float var  = stats[64 + c] / cnt - mean * mean;
        float s = g[c] * rsqrtf(var + 1e-5f);
        sc[c] = s;
        sh[c] = be[c] - mean * s;
    }
    __syncthreads();
    const int D3 = 32768;
    int v = blockIdx.x * 256 + threadIdx.x;
    int b = v / D3, r = v % D3;
    const float m = mo[v];
    u64 acc2[16];
#pragma unroll
    for (int k = 0; k < 16; k++) acc2[k] = 0ull;
    const float* xp = x + b * 64 * D3 + r;
#pragma unroll 8
    for (int ci = 0; ci < 64; ci++) {
        float zn = fmaf(*xp, sc[ci], sh[ci]); xp += D3;
        u64 xv = pack2(zn);
        const ulonglong2* w2 = reinterpret_cast<const ulonglong2*>(sw + ci * 32);
#pragma unroll
        for (int q = 0; q < 8; q++) {
            ulonglong2 w = w2[q];
            acc2[2 * q]     = ffma2(xv, w.x, acc2[2 * q]);
            acc2[2 * q + 1] = ffma2(xv, w.y, acc2[2 * q + 1]);
        }
    }
#pragma unroll
    for (int k = 0; k < 16; k++) {
        float2 a = unpack2(acc2[k]);
        out[(b * 32 + 2 * k)     * D3 + r] = fmaf(a.x, m, fb[2 * k]);
        out[(b * 32 + 2 * k + 1) * D3 + r] = fmaf(a.y, m, fb[2 * k + 1]);
    }
}

// ---------------------------------------------------------------------------
// Host launcher
// ---------------------------------------------------------------------------
extern "C" void kernel_launch(void* const* d_in, const int* in_sizes, int n_in,
                              void* d_out, int out_size) {
    (void)in_sizes; (void)n_in; (void)out_size;
    float* S = nullptr;
    cudaGetSymbolAddress((void**)&S, g_scratch);

    const float* feat = (const float*)d_in[0];
    const float* mask = (const float*)d_in[1];
    const float* w1  = (const float*)d_in[2];  const float* b1  = (const float*)d_in[3];
    const float* g1  = (const float*)d_in[4];  const float* be1 = (const float*)d_in[5];
    const float* w2  = (const float*)d_in[6];  const float* b2  = (const float*)d_in[7];
    const float* g2  = (const float*)d_in[8];  const float* be2 = (const float*)d_in[9];
    const float* w3  = (const float*)d_in[10]; const float* b3  = (const float*)d_in[11];
    const float* g3  = (const float*)d_in[12]; const float* be3 = (const float*)d_in[13];
    const float* tw1 = (const float*)d_in[14]; const float* tb1 = (const float*)d_in[15];
    const float* tg1 = (const float*)d_in[16]; const float* tbe1= (const float*)d_in[17];
    const float* tw2 = (const float*)d_in[18]; const float* tb2 = (const float*)d_in[19];
    const float* tg2 = (const float*)d_in[20]; const float* tbe2= (const float*)d_in[21];
    const float* fw  = (const float*)d_in[22]; const float* fb  = (const float*)d_in[23];
    float* out = (float*)d_out;

    float *x0 = S+OX0, *z1 = S+OZ1, *z2 = S+OZ2, *z3 = S+OZ3, *z4 = S+OZ4, *z5 = S+OZ5;
    float *m0p = S+OM0P, *m1 = S+OM1, *m2 = S+OM2, *m3 = S+OM3, *m4 = S+OM4, *m5 = S+OM5;
    float *w1T = S+OW1, *w2T = S+OW2, *w3T = S+OW3, *tw1T = S+OTW1, *tw2T = S+OTW2, *fwT = S+OFW;
    float *st = S+OST, *pb = S+OPB;

    // 1..3: prep; launch 4 = conv1 (the ncu-profiled slot)
    k_trans_all<<<8744, 256>>>(w1, w2, w3, tw1, tw2, fw, S);
    k_pre<<<2048, 256>>>(feat, mask, x0, m0p);
    k_maskd64p<<<128, 256>>>(m0p, m1, st + 0 * 260 + 64);

    // stage 1: 4 -> 32, 64^3 -> 32^3 (4-voxel x 8co threads, FULLW)
    k_conv_fwd2<4, 32, 64, 32, 1, true><<<dim3(64, 4), 256>>>(x0, w1T, b1, m1, z1, st + 0 * 260);
    // norm1 + fused m2 dilation (32 extra blocks)
    k_norm_mf<32, 16><<<8192 + 32, 256>>>(z1, m1, st + 0 * 260, g1, be1, 32, 32, 1,
                                          8192, m1, m2, st + 1 * 260 + 128);

    // stage 2: 32 -> 64, 32^3 -> 16^3, tz-split x4
    k_conv_fwd2<32, 64, 32, 16, 4, false><<<dim3(8, 8, 4), 256>>>(z1, w2T, b2, m2, pb, st + 1 * 260);
    // post2 + fused m3 dilation (4 extra blocks)
    k_post_mf<4, 16, 8><<<2048 + 4, 256>>>(pb, b2, m2, z2, st + 1 * 260, 64, 16, 1,
                                           2048, m2, m3, st + 2 * 260 + 256);
    k_norm<<<2048, 256>>>(z2, m2, st + 1 * 260, g2, be2, 64, 16, 1);

    // stage 3: 64 -> 128, 16^3 -> 8^3, (tz,ty)-split x16
    k_conv_fwd2<64, 128, 16, 8, 16, false><<<dim3(1, 16, 16), 256>>>(z2, w3T, b3, m3, pb, st + 2 * 260);
    // post3 + fused m4 (transpose) dilation (32 extra blocks)
    k_post_mt<16, 8, 16><<<512 + 32, 256>>>(pb, b3, m3, z3, st + 2 * 260, 128, 8, 1,
                                            512, m3, m4, st + 3 * 260 + 256);
    k_norm<<<512, 256>>>(z3, m3, st + 2 * 260, g3, be3, 128, 8, 1);

    // stage 4: tconv 128 -> 128, 8^3 -> 16^3, jp-split x4
    k_conv_t2<128, 128, 8, true, 4><<<dim3(2, 8, 32), 256>>>(z3, tw1T, tb1, m4, pb, st + 3 * 260);
    // post4 + fused m5 (transpose) dilation (256 extra blocks)
    k_post_mt<4, 16, 32><<<4096 + 256, 256>>>(pb, tb1, m4, z4, st + 3 * 260, 128, 16, 1,
                                              4096, m4, m5, st + 4 * 260 + 128);
    k_norm<<<4096, 256>>>(z4, m4, st + 3 * 260, tg1, tbe1, 128, 16, 1);

    // stage 5: tconv 128 -> 64, 16^3 -> 32^3, unsplit; BN-5 folded into head
    k_conv_t2<128, 64, 16, false, 1><<<dim3(16, 4, 8), 256>>>(z4, tw2T, tb2, m5, z5, st + 4 * 260);

    // head with fused BN-5
    k_head<<<256, 256>>>(z5, fwT, fb, st + 4 * 260, tg2, tbe2, m5, out);
}

// round 17
// speedup vs baseline: 1.2300x; 1.0648x over previous
#include <cuda_runtime.h>
#include <math.h>

typedef unsigned long long u64;

__device__ __forceinline__ u64 pack2(float v) {
    u64 r; asm("mov.b64 %0, {%1, %1};" : "=l"(r) : "f"(v)); return r;
}
__device__ __forceinline__ u64 ffma2(u64 a, u64 b, u64 c) {
    u64 d; asm("fma.rn.f32x2 %0, %1, %2, %3;" : "=l"(d) : "l"(a), "l"(b), "l"(c)); return d;
}
__device__ __forceinline__ float2 unpack2(u64 a) {
    float2 f; asm("mov.b64 {%0, %1}, %2;" : "=f"(f.x), "=f"(f.y) : "l"(a)); return f;
}

// ---------------------------------------------------------------------------
// Scratch arena. Activations halo-padded: dim D stored as P=D+2, interior
// voxel (z,y,x) at ((z+1)*P+(y+1))*P+(x+1). Halos are NEVER written -> stay 0.
// ---------------------------------------------------------------------------
constexpr int OX0  = 0;
constexpr int OZ1  = 2299968;
constexpr int OZ2  = 4815424;
constexpr int OZ3  = 5561920;
constexpr int OZ4  = 5817920;
constexpr int OZ5  = 7310912;
constexpr int OM0P = 11505216;
constexpr int OM1  = 12080208;
constexpr int OM2  = 12145744;
constexpr int OM3  = 12153936;
constexpr int OM4  = 12154960;
constexpr int OM5  = 12163152;
constexpr int OW1  = 12228688;
constexpr int OW2  = 12236880;
constexpr int OW3  = 12367952;
constexpr int OTW1 = 12892240;
constexpr int OTW2 = 13940816;
constexpr int OFW  = 14465104;
constexpr int OST  = 14467152;
constexpr int OPB  = 14468452;
constexpr int TOT_SCRATCH = 22857216;

__device__ __align__(16) float g_scratch[TOT_SCRATCH];

// weight transposes + stats zeroing
__global__ void k_trans_all(const float* __restrict__ w1, const float* __restrict__ w2,
                            const float* __restrict__ w3, const float* __restrict__ tw1,
                            const float* __restrict__ tw2, const float* __restrict__ fw,
                            float* __restrict__ S) {
    int idx = blockIdx.x * 256 + threadIdx.x;
    if (idx < 5 * 260) S[OST + idx] = 0.f;
    const float* src; float* dst; int CI, CO, i = idx;
    if (i < 8192)            { src = w1;  dst = S + OW1;  CI = 4;   CO = 32;  }
    else if ((i -= 8192)  < 131072)  { src = w2;  dst = S + OW2;  CI = 32;  CO = 64;  }
    else if ((i -= 131072) < 524288) { src = w3;  dst = S + OW3;  CI = 64;  CO = 128; }
    else if ((i -= 524288) < 1048576){ src = tw1; dst = S + OTW1; CI = 128; CO = 128; }
    else if ((i -= 1048576)< 524288) { src = tw2; dst = S + OTW2; CI = 128; CO = 64;  }
    else if ((i -= 524288) < 2048)   { S[OFW + (i % 64) * 32 + i / 64] = fw[i]; return; }
    else return;
    int t = i & 63, ci = (i >> 6) % CI, co = i / (64 * CI);
    dst[(t * CI + ci) * CO + co] = src[i];
}

// masked input into padded x0 + padded m0p
__global__ void k_pre(const float* __restrict__ feat, const float* __restrict__ mask,
                      float* __restrict__ x0, float* __restrict__ m0p) {
    int v = blockIdx.x * 256 + threadIdx.x;
    float m = mask[v] > 0.5f ? 1.f : 0.f;
    int b = v >> 18, r = v & 262143;
    int z = r >> 12, y = (r >> 6) & 63, x = r & 63;
    int poff = ((z + 1) * 66 + (y + 1)) * 66 + (x + 1);
    m0p[b * 287496 + poff] = m;
#pragma unroll
    for (int c = 0; c < 4; c++)
        x0[(b * 4 + c) * 287496 + poff] = feat[(b * 4 + c) * 262144 + r] * m;
}

// mask dilation 64^3->32^3 from PADDED m0p, branch-free, 2 voxels/thread
__global__ void k_maskd64p(const float* __restrict__ m0p, float* __restrict__ mo,
                           float* __restrict__ cnt) {
    int v = blockIdx.x * 256 + threadIdx.x;
    int b = v / 16384, rp = v % 16384;
    int r = 2 * rp;
    int oz = r >> 10, oy = (r >> 5) & 31, ox = r & 31;
    const float* base = m0p + b * 287496 + (2 * oz) * 4356 + (2 * oy) * 66 + 2 * ox;
    float sA = 0.f, sB = 0.f;
#pragma unroll
    for (int tz = 0; tz < 4; tz++)
#pragma unroll
        for (int ty = 0; ty < 4; ty++) {
            const float* p = base + tz * 4356 + ty * 66;
            float w0 = __ldg(p), w1 = __ldg(p + 1), w2 = __ldg(p + 2);
            float w3 = __ldg(p + 3), w4 = __ldg(p + 4), w5 = __ldg(p + 5);
            float c = w2 + w3;
            sA += w0 + w1 + c;
            sB += c + w4 + w5;
        }
    float aA = sA > 0.f ? 1.f : 0.f, aB = sB > 0.f ? 1.f : 0.f;
    mo[b * 32768 + r] = aA;
    mo[b * 32768 + r + 1] = aB;
    float s = aA + aB;
    for (int o = 16; o; o >>= 1) s += __shfl_xor_sync(0xffffffffu, s, o);
    if ((threadIdx.x & 31) == 0) atomicAdd(cnt, s);
}

// ---------------------------------------------------------------------------
// Mask dilation device bodies (used by fused kernels' extra blocks)
// ---------------------------------------------------------------------------
template <int DI, int DO>
__device__ __forceinline__ void maskd_fwd_body(int blk, const float* __restrict__ mi,
                                               float* __restrict__ mo, float* __restrict__ cnt) {
    const int DO3 = DO * DO * DO, DI2 = DI * DI, DI3 = DI * DI * DI;
    int v = blk * 256 + threadIdx.x;
    int b = v / DO3, r = v % DO3;
    int oz = r / (DO * DO), oy = (r / DO) % DO, ox = r % DO;
    float m = 0.f;
    for (int tz = 0; tz < 4; tz++) {
        int iz = 2 * oz - 1 + tz;
        if ((unsigned)iz >= DI) continue;
        for (int ty = 0; ty < 4; ty++) {
            int iy = 2 * oy - 1 + ty;
            if ((unsigned)iy >= DI) continue;
            const float* p = mi + b * DI3 + iz * DI2 + iy * DI;
            for (int tx = 0; tx < 4; tx++) {
                int ix = 2 * ox - 1 + tx;
                if ((unsigned)ix < DI) m += p[ix];
            }
        }
    }
    float act = m > 0.f ? 1.f : 0.f;
    mo[v] = act;
    float s = act;
    for (int o = 16; o; o >>= 1) s += __shfl_xor_sync(0xffffffffu, s, o);
    if ((threadIdx.x & 31) == 0) atomicAdd(cnt, s);
}

template <int DI, int DO>
__device__ __forceinline__ void maskd_t_body(int blk, const float* __restrict__ mi,
                                             float* __restrict__ mo, float* __restrict__ cnt) {
    const int DO3 = DO * DO * DO, DI2 = DI * DI, DI3 = DI * DI * DI;
    int v = blk * 256 + threadIdx.x;
    int b = v / DO3, r = v % DO3;
    int oz = r / (DO * DO), oy = (r / DO) % DO, ox = r % DO;
    int izl[2], iyl[2], ixl[2];
    izl[0] = oz >> 1; izl[1] = (oz & 1) ? (oz >> 1) + 1 : (oz >> 1) - 1;
    iyl[0] = oy >> 1; iyl[1] = (oy & 1) ? (oy >> 1) + 1 : (oy >> 1) - 1;
    ixl[0] = ox >> 1; ixl[1] = (ox & 1) ? (ox >> 1) + 1 : (ox >> 1) - 1;
    float m = 0.f;
#pragma unroll
    for (int jz = 0; jz < 2; jz++) {
        int iz = izl[jz];
        if ((unsigned)iz >= DI) continue;
#pragma unroll
        for (int jy = 0; jy < 2; jy++) {
            int iy = iyl[jy];
            if ((unsigned)iy >= DI) continue;
#pragma unroll
            for (int jx = 0; jx < 2; jx++) {
                int ix = ixl[jx];
                if ((unsigned)ix < DI) m += mi[b * DI3 + iz * DI2 + iy * DI + ix];
            }
        }
    }
    float act = m > 0.f ? 1.f : 0.f;
    mo[v] = act;
    float s = act;
    for (int o = 16; o; o >>= 1) s += __shfl_xor_sync(0xffffffffu, s, o);
    if ((threadIdx.x & 31) == 0) atomicAdd(cnt, s);
}

// ---------------------------------------------------------------------------
// Forward conv, 4 adjacent output voxels x 8 co per thread. NT = block size.
// FULLW (small CI): stage all 64 taps once, zero in-loop syncs.
// SPLIT=1: full conv + epilogue. SPLIT=4: tz-split. SPLIT=16: (tz,ty)-split.
// ---------------------------------------------------------------------------
template <int CI, int CO, int DI, int DO, int SPLIT, bool FULLW, int NT>
__global__ void __launch_bounds__(NT) k_conv_fwd2(
    const float* __restrict__ x, const float* __restrict__ wT,
    const float* __restrict__ bias, const float* __restrict__ mo,
    float* __restrict__ zout, float* __restrict__ stats) {
    constexpr int PI = DI + 2, PO = DO + 2;
    constexpr int PI2 = PI * PI, PI3 = PI2 * PI, PO3 = PO * PO * PO;
    constexpr int DO3 = DO * DO * DO, QDO3 = DO3 / 4;
    constexpr int NTAP = FULLW ? 64 : ((SPLIT == 16) ? 4 : 16);
    __shared__ __align__(16) float sw[NTAP * CI * 8];
    const int co0 = blockIdx.y * 8;
    const int v = blockIdx.x * NT + threadIdx.x;
    const int b = v / QDO3, rp = v % QDO3;
    const int r = 4 * rp;
    const int oz = r / (DO * DO), oy = (r / DO) % DO, ox = r % DO;
    u64 acc[4][4];
#pragma unroll
    for (int vv = 0; vv < 4; vv++)
#pragma unroll
        for (int p = 0; p < 4; p++) acc[vv][p] = 0ull;
    const float* xbase = x + (b * CI) * PI3 + (2 * oz) * PI2 + (2 * oy) * PI + 2 * ox;

    auto stage = [&](int t0, int ntap) {
        for (int i = threadIdx.x; i < ntap * CI * 8; i += NT) {
            int k = i & 7, ci = (i >> 3) % CI, s = i / (8 * CI);
            sw[i] = wT[((t0 + s) * CI + ci) * CO + co0 + k];
        }
    };
    auto body = [&](int tz, int ty, const float* swrow) {
        const float* xr = xbase + tz * PI2 + ty * PI;
#pragma unroll 4
        for (int ci = 0; ci < CI; ci++) {
            const float* xp = xr + ci * PI3;
            float2 q0 = *reinterpret_cast<const float2*>(xp);
            float2 q1 = *reinterpret_cast<const float2*>(xp + 2);
            float2 q2 = *reinterpret_cast<const float2*>(xp + 4);
            float2 q3 = *reinterpret_cast<const float2*>(xp + 6);
            float2 q4 = *reinterpret_cast<const float2*>(xp + 8);
            u64 p[10];
            p[0] = pack2(q0.x); p[1] = pack2(q0.y); p[2] = pack2(q1.x);
            p[3] = pack2(q1.y); p[4] = pack2(q2.x); p[5] = pack2(q2.y);
            p[6] = pack2(q3.x); p[7] = pack2(q3.y); p[8] = pack2(q4.x);
            p[9] = pack2(q4.y);
#pragma unroll
            for (int tx = 0; tx < 4; tx++) {
                const float* wp = swrow + (tx * CI + ci) * 8;
                ulonglong2 w0 = *reinterpret_cast<const ulonglong2*>(wp);
                ulonglong2 w1 = *reinterpret_cast<const ulonglong2*>(wp + 4);
#pragma unroll
                for (int vv = 0; vv < 4; vv++) {
                    acc[vv][0] = ffma2(p[2 * vv + tx], w0.x, acc[vv][0]);
                    acc[vv][1] = ffma2(p[2 * vv + tx], w0.y, acc[vv][1]);
                    acc[vv][2] = ffma2(p[2 * vv + tx], w1.x, acc[vv][2]);
                    acc[vv][3] = ffma2(p[2 * vv + tx], w1.y, acc[vv][3]);
                }
            }
        }
    };

    if constexpr (SPLIT == 1) {
        if constexpr (FULLW) {
            stage(0, 64);
            __syncthreads();
            for (int tz = 0; tz < 4; tz++)
                for (int ty = 0; ty < 4; ty++)
                    body(tz, ty, sw + (tz * 16 + ty * 4) * CI * 8);
        } else {
            for (int tz = 0; tz < 4; tz++) {
                __syncthreads();
                stage(tz * 16, 16);
                __syncthreads();
                for (int ty = 0; ty < 4; ty++) body(tz, ty, sw + (ty * 4) * CI * 8);
            }
        }
    } else if constexpr (SPLIT == 4) {
        const int tz = blockIdx.z;
        stage(tz * 16, 16);
        __syncthreads();
        for (int ty = 0; ty < 4; ty++) body(tz, ty, sw + (ty * 4) * CI * 8);
    } else {
        const int tz = blockIdx.z >> 2, ty = blockIdx.z & 3;
        stage(tz * 16 + ty * 4, 4);
        __syncthreads();
        body(tz, ty, sw);
    }

    if constexpr (SPLIT == 1) {
        __shared__ float ssum[8], ssq[8];
        float mk[4];
#pragma unroll
        for (int vv = 0; vv < 4; vv++) mk[vv] = mo[b * DO3 + r + vv];
        const int poffA = ((oz + 1) * PO + (oy + 1)) * PO + (ox + 1);
        float s8[8], q8[8];
#pragma unroll
        for (int p = 0; p < 4; p++) {
            float bi0 = bias[co0 + 2 * p], bi1 = bias[co0 + 2 * p + 1];
            float y0[4], y1[4];
#pragma unroll
            for (int vv = 0; vv < 4; vv++) {
                float2 a = unpack2(acc[vv][p]);
                float t0 = (a.x + bi0) * mk[vv];
                float t1 = (a.y + bi1) * mk[vv];
                y0[vv] = t0 >= 0.f ? t0 : 0.01f * t0;
                y1[vv] = t1 >= 0.f ? t1 : 0.01f * t1;
            }
            float* zp0 = zout + (b * CO + co0 + 2 * p) * PO3 + poffA;
            float* zp1 = zp0 + PO3;
#pragma unroll
            for (int vv = 0; vv < 4; vv++) { zp0[vv] = y0[vv]; zp1[vv] = y1[vv]; }
            s8[2*p]   = y0[0] + y0[1] + y0[2] + y0[3];
            q8[2*p]   = y0[0]*y0[0] + y0[1]*y0[1] + y0[2]*y0[2] + y0[3]*y0[3];
            s8[2*p+1] = y1[0] + y1[1] + y1[2] + y1[3];
            q8[2*p+1] = y1[0]*y1[0] + y1[1]*y1[1] + y1[2]*y1[2] + y1[3]*y1[3];
        }
        __syncthreads();
        if (threadIdx.x < 8) { ssum[threadIdx.x] = 0.f; ssq[threadIdx.x] = 0.f; }
        __syncthreads();
#pragma unroll
        for (int k = 0; k < 8; k++) {
            float s = s8[k], q = q8[k];
            for (int o = 16; o; o >>= 1) {
                s += __shfl_xor_sync(0xffffffffu, s, o);
                q += __shfl_xor_sync(0xffffffffu, q, o);
            }
            if ((threadIdx.x & 31) == 0) { atomicAdd(&ssum[k], s); atomicAdd(&ssq[k], q); }
        }
        __syncthreads();
        if (threadIdx.x < 8)
            atomicAdd(&stats[co0 + threadIdx.x], ssum[threadIdx.x]);
        else if (threadIdx.x < 16)
            atomicAdd(&stats[CO + co0 + threadIdx.x - 8], ssq[threadIdx.x - 8]);
    } else {
        float* pb = zout + ((blockIdx.z * 2 + b) * CO) * DO3 + r;
#pragma unroll
        for (int p = 0; p < 4; p++) {
            float2 a0 = unpack2(acc[0][p]);
            float2 a1 = unpack2(acc[1][p]);
            float2 a2 = unpack2(acc[2][p]);
            float2 a3 = unpack2(acc[3][p]);
            *reinterpret_cast<float4*>(pb + (co0 + 2 * p) * DO3)
                = make_float4(a0.x, a1.x, a2.x, a3.x);
            *reinterpret_cast<float4*>(pb + (co0 + 2 * p + 1) * DO3)
                = make_float4(a0.y, a1.y, a2.y, a3.y);
        }
    }
}

// ---------------------------------------------------------------------------
// Transpose conv, 2 adjacent input voxels x 16 co per thread. NT = block size.
// ---------------------------------------------------------------------------
template <int CI, int CO, int DI, bool PADOUT, int SLOTS, int NT>
__global__ void __launch_bounds__(NT) k_conv_t2(
    const float* __restrict__ x, const float* __restrict__ wT,
    const float* __restrict__ bias, const float* __restrict__ mo,
    float* __restrict__ zout, float* __restrict__ stats) {
    constexpr int DO = 2 * DI, PI = DI + 2, PO = DO + 2;
    constexpr int PI2 = PI * PI, PI3 = PI2 * PI;
    constexpr int DI2 = DI * DI, DI3 = DI2 * DI, DO3 = DO * DO * DO;
    constexpr int PO3 = PO * PO * PO, HDI3 = DI3 / 2;
    constexpr int NJP = 4 / SLOTS;
    __shared__ __align__(16) float sw[2 * CI * 16];
    const int cls = (SLOTS == 1) ? blockIdx.z : (blockIdx.z & 7);
    const int jp0 = (SLOTS == 1) ? 0 : (blockIdx.z >> 3);
    const int pz = (cls >> 2) & 1, py = (cls >> 1) & 1, px = cls & 1;
    const int cog = blockIdx.y * 16;
    const int v = blockIdx.x * NT + threadIdx.x;
    const int b = v / HDI3, rp = v % HDI3;
    const int r = 2 * rp;
    const int zi = r / DI2, yi = (r / DI) % DI, xi = r % DI;

    u64 aA[8], aB[8];
#pragma unroll
    for (int k = 0; k < 8; k++) { aA[k] = 0ull; aB[k] = 0ull; }

    const int sxp = (px ? xi : xi - 1) + 1;

    for (int jj = 0; jj < NJP; jj++) {
        const int jp = jp0 * NJP + jj;
        const int jz = jp >> 1, jy = jp & 1;
        const int tz = pz ? 2 - 2 * jz : 1 + 2 * jz;
        const int ty = py ? 2 - 2 * jy : 1 + 2 * jy;
        if (jj) __syncthreads();
        for (int i = threadIdx.x; i < 2 * CI * 16; i += NT) {
            int k = i & 15, ci = (i >> 4) % CI, jx = i / (16 * CI);
            int tx = px ? 2 - 2 * jx : 1 + 2 * jx;
            sw[i] = wT[((tz * 16 + ty * 4 + tx) * CI + ci) * CO + cog + k];
        }
        __syncthreads();
        const int iz = pz ? zi + jz : zi - jz;
        const int iy = py ? yi + jy : yi - jy;
        const float* xr = x + (b * CI) * PI3 + (iz + 1) * PI2 + (iy + 1) * PI + sxp;
#pragma unroll 4
        for (int ci = 0; ci < CI; ci++) {
            const float* xp = xr + ci * PI3;
            u64 p0 = pack2(xp[0]), p1 = pack2(xp[1]), p2 = pack2(xp[2]);
            {
                const float* wp = sw + ci * 16;
                ulonglong2 w0 = *reinterpret_cast<const ulonglong2*>(wp);
                ulonglong2 w1 = *reinterpret_cast<const ulonglong2*>(wp + 4);
                ulonglong2 w2 = *reinterpret_cast<const ulonglong2*>(wp + 8);
                ulonglong2 w3 = *reinterpret_cast<const ulonglong2*>(wp + 12);
                u64 xA = px ? p0 : p1;
                u64 xB = px ? p1 : p2;
                aA[0] = ffma2(xA, w0.x, aA[0]); aA[1] = ffma2(xA, w0.y, aA[1]);
                aA[2] = ffma2(xA, w1.x, aA[2]); aA[3] = ffma2(xA, w1.y, aA[3]);
                aA[4] = ffma2(xA, w2.x, aA[4]); aA[5] = ffma2(xA, w2.y, aA[5]);
                aA[6] = ffma2(xA, w3.x, aA[6]); aA[7] = ffma2(xA, w3.y, aA[7]);
                aB[0] = ffma2(xB, w0.x, aB[0]); aB[1] = ffma2(xB, w0.y, aB[1]);
                aB[2] = ffma2(xB, w1.x, aB[2]); aB[3] = ffma2(xB, w1.y, aB[3]);
                aB[4] = ffma2(xB, w2.x, aB[4]); aB[5] = ffma2(xB, w2.y, aB[5]);
                aB[6] = ffma2(xB, w3.x, aB[6]); aB[7] = ffma2(xB, w3.y, aB[7]);
            }
            {
                const float* wp = sw + (CI + ci) * 16;
                ulonglong2 w0 = *reinterpret_cast<const ulonglong2*>(wp);
                ulonglong2 w1 = *reinterpret_cast<const ulonglong2*>(wp + 4);
                ulonglong2 w2 = *reinterpret_cast<const ulonglong2*>(wp + 8);
                ulonglong2 w3 = *reinterpret_cast<const ulonglong2*>(wp + 12);
                u64 xA = px ? p1 : p0;
                u64 xB = px ? p2 : p1;
                aA[0] = ffma2(xA, w0.x, aA[0]); aA[1] = ffma2(xA, w0.y, aA[1]);
                aA[2] = ffma2(xA, w1.x, aA[2]); aA[3] = ffma2(xA, w1.y, aA[3]);
                aA[4] = ffma2(xA, w2.x, aA[4]); aA[5] = ffma2(xA, w2.y, aA[5]);
                aA[6] = ffma2(xA, w3.x, aA[6]); aA[7] = ffma2(xA, w3.y, aA[7]);
                aB[0] = ffma2(xB, w0.x, aB[0]); aB[1] = ffma2(xB, w0.y, aB[1]);
                aB[2] = ffma2(xB, w1.x, aB[2]); aB[3] = ffma2(xB, w1.y, aB[3]);
                aB[4] = ffma2(xB, w2.x, aB[4]); aB[5] = ffma2(xB, w2.y, aB[5]);
                aB[6] = ffma2(xB, w3.x, aB[6]); aB[7] = ffma2(xB, w3.y, aB[7]);
            }
        }
    }

    const int oz = 2 * zi + pz, oy = 2 * yi + py;
    const int oxA = 2 * xi + px;
    const int roA = (oz * DO + oy) * DO + oxA;

    if constexpr (SLOTS == 1) {
        __shared__ float ssum[16], ssq[16];
        const float mA = mo[b * DO3 + roA], mB = mo[b * DO3 + roA + 2];
        const int ooffA = PADOUT ? ((oz + 1) * PO + (oy + 1)) * PO + (oxA + 1) : roA;
        const int ostr  = PADOUT ? PO3 : DO3;
        float zsA[16], zsB[16];
#pragma unroll
        for (int p = 0; p < 8; p++) {
            float2 a = unpack2(aA[p]);
            float2 bb = unpack2(aB[p]);
            float bi0 = bias[cog + 2 * p], bi1 = bias[cog + 2 * p + 1];
            float yA0 = (a.x + bi0) * mA, yA1 = (a.y + bi1) * mA;
            float yB0 = (bb.x + bi0) * mB, yB1 = (bb.y + bi1) * mB;
            zsA[2*p]   = yA0 >= 0.f ? yA0 : 0.01f * yA0;
            zsA[2*p+1] = yA1 >= 0.f ? yA1 : 0.01f * yA1;
            zsB[2*p]   = yB0 >= 0.f ? yB0 : 0.01f * yB0;
            zsB[2*p+1] = yB1 >= 0.f ? yB1 : 0.01f * yB1;
            float* zp0 = zout + (b * CO + cog + 2 * p) * ostr + ooffA;
            float* zp1 = zout + (b * CO + cog + 2 * p + 1) * ostr + ooffA;
            zp0[0] = zsA[2*p];   zp0[2] = zsB[2*p];
            zp1[0] = zsA[2*p+1]; zp1[2] = zsB[2*p+1];
        }
        __syncthreads();
        if (threadIdx.x < 16) { ssum[threadIdx.x] = 0.f; ssq[threadIdx.x] = 0.f; }
        __syncthreads();
#pragma unroll
        for (int k = 0; k < 16; k++) {
            float s = zsA[k] + zsB[k];
            float q = zsA[k] * zsA[k] + zsB[k] * zsB[k];
            for (int o = 16; o; o >>= 1) {
                s += __shfl_xor_sync(0xffffffffu, s, o);
                q += __shfl_xor_sync(0xffffffffu, q, o);
            }
            if ((threadIdx.x & 31) == 0) { atomicAdd(&ssum[k], s); atomicAdd(&ssq[k], q); }
        }
        __syncthreads();
        if (threadIdx.x < 16)
            atomicAdd(&stats[cog + threadIdx.x], ssum[threadIdx.x]);
        else if (threadIdx.x < 32)
            atomicAdd(&stats[CO + cog + threadIdx.x - 16], ssq[threadIdx.x - 16]);
    } else {
        float* pb = zout + ((jp0 * 2 + b) * CO) * DO3;
#pragma unroll
        for (int p = 0; p < 8; p++) {
            float2 a = unpack2(aA[p]);
            float2 bb = unpack2(aB[p]);
            pb[(cog + 2 * p)     * DO3 + roA]     = a.x;
            pb[(cog + 2 * p + 1) * DO3 + roA]     = a.y;
            pb[(cog + 2 * p)     * DO3 + roA + 2] = bb.x;
            pb[(cog + 2 * p + 1) * DO3 + roA + 2] = bb.y;
        }
    }
}

// ---------------------------------------------------------------------------
// Post body (sum partials + bias + mask + leaky + padded store + stats)
// ---------------------------------------------------------------------------
template <int NS>
__device__ __forceinline__ void post_body(int blk, const float* __restrict__ pbuf,
                                          const float* __restrict__ bias,
                                          const float* __restrict__ mo, float* __restrict__ z,
                                          float* __restrict__ stats, int CO, int D, int pd) {
    const int D3 = D * D * D;
    int idx = blk * 256 + threadIdx.x;
    int r = idx % D3, c = (idx / D3) % CO, b = idx / (D3 * CO);
    float s = 0.f;
#pragma unroll
    for (int j = 0; j < NS; j++) s += pbuf[((j * 2 + b) * CO + c) * D3 + r];
    float m = mo[b * D3 + r];
    float y = (s + bias[c]) * m;
    y = y >= 0.f ? y : 0.01f * y;
    int P = D + 2 * pd, P3 = P * P * P;
    int rz = r / (D * D), ry = (r / D) % D, rx = r % D;
    z[(b * CO + c) * P3 + ((rz + pd) * P + (ry + pd)) * P + (rx + pd)] = y;
    float ss = y, q = y * y;
    for (int o = 16; o; o >>= 1) {
        ss += __shfl_xor_sync(0xffffffffu, ss, o);
        q  += __shfl_xor_sync(0xffffffffu, q, o);
    }
    if ((threadIdx.x & 31) == 0) { atomicAdd(&stats[c], ss); atomicAdd(&stats[CO + c], q); }
}

template <int NS, int MDI, int MDO>
__global__ void k_post_mf(const float* __restrict__ pbuf, const float* __restrict__ bias,
                          const float* __restrict__ mo, float* __restrict__ z,
                          float* __restrict__ stats, int CO, int D, int pd, int mainBlocks,
                          const float* __restrict__ mi, float* __restrict__ mnext,
                          float* __restrict__ cnt) {
    if ((int)blockIdx.x >= mainBlocks) {
        maskd_fwd_body<MDI, MDO>(blockIdx.x - mainBlocks, mi, mnext, cnt);
        return;
    }
    post_body<NS>(blockIdx.x, pbuf, bias, mo, z, stats, CO, D, pd);
}

template <int NS, int MDI, int MDO>
__global__ void k_post_mt(const float* __restrict__ pbuf, const float* __restrict__ bias,
                          const float* __restrict__ mo, float* __restrict__ z,
                          float* __restrict__ stats, int CO, int D, int pd, int mainBlocks,
                          const float* __restrict__ mi, float* __restrict__ mnext,
                          float* __restrict__ cnt) {
    if ((int)blockIdx.x >= mainBlocks) {
        maskd_t_body<MDI, MDO>(blockIdx.x - mainBlocks, mi, mnext, cnt);
        return;
    }
    post_body<NS>(blockIdx.x, pbuf, bias, mo, z, stats, CO, D, pd);
}

// ---------------------------------------------------------------------------
// BN apply with inline finalize (+ optional fused fwd-dilation blocks)
// ---------------------------------------------------------------------------
__device__ __forceinline__ void norm_body(int blk, float* __restrict__ z,
                                          const float* __restrict__ mo,
                                          const float* __restrict__ stats,
                                          const float* __restrict__ g,
                                          const float* __restrict__ be,
                                          int CO, int D, int pd) {
    __shared__ float sc[128], sh[128];
    if (threadIdx.x < CO) {
        int c = threadIdx.x;
        float cnt  = fmaxf(stats[2 * CO], 1.f);
        float mean = stats[c] / cnt;
        float var  = stats[CO + c] / cnt - mean * mean;
        float s = g[c] * rsqrtf(var + 1e-5f);
        sc[c] = s;
        sh[c] = be[c] - mean * s;
    }
    __syncthreads();
    const int D3 = D * D * D, P = D + 2 * pd, P3 = P * P * P;
    int idx = blk * 256 + threadIdx.x;
    int c = (idx / D3) % CO, b = idx / (D3 * CO), r = idx % D3;
    int rz = r / (D * D), ry = (r / D) % D, rx = r % D;
    int off = (b * CO + c) * P3 + ((rz + pd) * P + (ry + pd)) * P + (rx + pd);
    z[off] = fmaf(z[off], sc[c], sh[c]) * mo[b * D3 + r];
}

__global__ void k_norm(float* __restrict__ z, const float* __restrict__ mo,
                       const float* __restrict__ stats, const float* __restrict__ g,
                       const float* __restrict__ be, int CO, int D, int pd) {
    norm_body(blockIdx.x, z, mo, stats, g, be, CO, D, pd);
}

template <int MDI, int MDO>
__global__ void k_norm_mf(float* __restrict__ z, const float* __restrict__ mo,
                          const float* __restrict__ stats, const float* __restrict__ g,
                          const float* __restrict__ be, int CO, int D, int pd,
                          int mainBlocks, const float* __restrict__ mi,
                          float* __restrict__ mnext, float* __restrict__ cnt) {
    if ((int)blockIdx.x >= mainBlocks) {
        maskd_fwd_body<MDI, MDO>(blockIdx.x - mainBlocks, mi, mnext, cnt);
        return;
    }
    norm_body(blockIdx.x, z, mo, stats, g, be, CO, D, pd);
}

// ---------------------------------------------------------------------------
// Head fused with BN-5: out = m * sum_ci fw[ci]*(z*sc[ci]+sh[ci]) + fb
// ---------------------------------------------------------------------------
__global__ void __launch_bounds__(256) k_head(const float* __restrict__ x,
                                              const float* __restrict__ fwT,
                                              const float* __restrict__ fb,
                                              const float* __restrict__ stats,
                                              const float* __restrict__ g,
                                              const float* __restrict__ be,
                                              const float* __restrict__ mo,
                                              float* __restrict__ out) {
    __shared__ __align__(16) float sw[64 * 32];
    __shared__ float sc[64], sh[64];
    for (int i = threadIdx.x; i < 2048; i += 256) sw[i] = fwT[i];
    if (threadIdx.x < 64) {
        int c = threadIdx.x;
        float cnt  = fmaxf(stats[128], 1.f);
        float mean = stats[c] / cnt;
        float var  = stats[64 + c] / cnt - mean * mean;
        float s = g[c] * rsqrtf(var + 1e-5f);
        sc[c] = s;
        sh[c] = be[c] - mean * s;
    }
    __syncthreads();
    const int D3 = 32768;
    int v = blockIdx.x * 256 + threadIdx.x;
    int b = v / D3, r = v % D3;
    const float m = mo[v];
    u64 acc2[16];
#pragma unroll
    for (int k = 0; k < 16; k++) acc2[k] = 0ull;
    const float* xp = x + b * 64 * D3 + r;
#pragma unroll 8
    for (int ci = 0; ci < 64; ci++) {
        float zn = fmaf(*xp, sc[ci], sh[ci]); xp += D3;
        u64 xv = pack2(zn);
        const ulonglong2* w2 = reinterpret_cast<const ulonglong2*>(sw + ci * 32);
#pragma unroll
        for (int q = 0; q < 8; q++) {
            ulonglong2 w = w2[q];
            acc2[2 * q]     = ffma2(xv, w.x, acc2[2 * q]);
            acc2[2 * q + 1] = ffma2(xv, w.y, acc2[2 * q + 1]);
        }
    }
#pragma unroll
    for (int k = 0; k < 16; k++) {
        float2 a = unpack2(acc2[k]);
        out[(b * 32 + 2 * k)     * D3 + r] = fmaf(a.x, m, fb[2 * k]);
        out[(b * 32 + 2 * k + 1) * D3 + r] = fmaf(a.y, m, fb[2 * k + 1]);
    }
}

// ---------------------------------------------------------------------------
// Host launcher
// ---------------------------------------------------------------------------
extern "C" void kernel_launch(void* const* d_in, const int* in_sizes, int n_in,
                              void* d_out, int out_size) {
    (void)in_sizes; (void)n_in; (void)out_size;
    float* S = nullptr;
    cudaGetSymbolAddress((void**)&S, g_scratch);

    const float* feat = (const float*)d_in[0];
    const float* mask = (const float*)d_in[1];
    const float* w1  = (const float*)d_in[2];  const float* b1  = (const float*)d_in[3];
    const float* g1  = (const float*)d_in[4];  const float* be1 = (const float*)d_in[5];
    const float* w2  = (const float*)d_in[6];  const float* b2  = (const float*)d_in[7];
    const float* g2  = (const float*)d_in[8];  const float* be2 = (const float*)d_in[9];
    const float* w3  = (const float*)d_in[10]; const float* b3  = (const float*)d_in[11];
    const float* g3  = (const float*)d_in[12]; const float* be3 = (const float*)d_in[13];
    const float* tw1 = (const float*)d_in[14]; const float* tb1 = (const float*)d_in[15];
    const float* tg1 = (const float*)d_in[16]; const float* tbe1= (const float*)d_in[17];
    const float* tw2 = (const float*)d_in[18]; const float* tb2 = (const float*)d_in[19];
    const float* tg2 = (const float*)d_in[20]; const float* tbe2= (const float*)d_in[21];
    const float* fw  = (const float*)d_in[22]; const float* fb  = (const float*)d_in[23];
    float* out = (float*)d_out;

    float *x0 = S+OX0, *z1 = S+OZ1, *z2 = S+OZ2, *z3 = S+OZ3, *z4 = S+OZ4, *z5 = S+OZ5;
    float *m0p = S+OM0P, *m1 = S+OM1, *m2 = S+OM2, *m3 = S+OM3, *m4 = S+OM4, *m5 = S+OM5;
    float *w1T = S+OW1, *w2T = S+OW2, *w3T = S+OW3, *tw1T = S+OTW1, *tw2T = S+OTW2, *fwT = S+OFW;
    float *st = S+OST, *pb = S+OPB;

    // 1..3: prep; launch 4 = conv1 (the ncu-profiled slot)
    k_trans_all<<<8744, 256>>>(w1, w2, w3, tw1, tw2, fw, S);
    k_pre<<<2048, 256>>>(feat, mask, x0, m0p);
    k_maskd64p<<<128, 256>>>(m0p, m1, st + 0 * 260 + 64);

    // stage 1: 4 -> 32, 64^3 -> 32^3, 128-thread CTAs -> 512 CTAs
    k_conv_fwd2<4, 32, 64, 32, 1, true, 128><<<dim3(128, 4), 128>>>(x0, w1T, b1, m1, z1, st + 0 * 260);
    k_norm_mf<32, 16><<<8192 + 32, 256>>>(z1, m1, st + 0 * 260, g1, be1, 32, 32, 1,
                                          8192, m1, m2, st + 1 * 260 + 128);

    // stage 2: 32 -> 64, 32^3 -> 16^3, tz-split x4, 128-thr -> 512 CTAs
    k_conv_fwd2<32, 64, 32, 16, 4, false, 128><<<dim3(16, 8, 4), 128>>>(z1, w2T, b2, m2, pb, st + 1 * 260);
    k_post_mf<4, 16, 8><<<2048 + 4, 256>>>(pb, b2, m2, z2, st + 1 * 260, 64, 16, 1,
                                           2048, m2, m3, st + 2 * 260 + 256);
    k_norm<<<2048, 256>>>(z2, m2, st + 1 * 260, g2, be2, 64, 16, 1);

    // stage 3: 64 -> 128, 16^3 -> 8^3, (tz,ty)-split x16, 128-thr -> 512 CTAs
    k_conv_fwd2<64, 128, 16, 8, 16, false, 128><<<dim3(2, 16, 16), 128>>>(z2, w3T, b3, m3, pb, st + 2 * 260);
    k_post_mt<16, 8, 16><<<512 + 32, 256>>>(pb, b3, m3, z3, st + 2 * 260, 128, 8, 1,
                                            512, m3, m4, st + 3 * 260 + 256);
    k_norm<<<512, 256>>>(z3, m3, st + 2 * 260, g3, be3, 128, 8, 1);

    // stage 4: tconv 128 -> 128, 8^3 -> 16^3, jp-split x4, 128-thr -> 1024 CTAs
    k_conv_t2<128, 128, 8, true, 4, 128><<<dim3(4, 8, 32), 128>>>(z3, tw1T, tb1, m4, pb, st + 3 * 260);
    k_post_mt<4, 16, 32><<<4096 + 256, 256>>>(pb, tb1, m4, z4, st + 3 * 260, 128, 16, 1,
                                              4096, m4, m5, st + 4 * 260 + 128);
    k_norm<<<4096, 256>>>(z4, m4, st + 3 * 260, tg1, tbe1, 128, 16, 1);

    // stage 5: tconv 128 -> 64, 16^3 -> 32^3, unsplit, 128-thr -> 1024 CTAs
    k_conv_t2<128, 64, 16, false, 1, 128><<<dim3(32, 4, 8), 128>>>(z4, tw2T, tb2, m5, z5, st + 4 * 260);

    // head with fused BN-5
    k_head<<<256, 256>>>(z5, fwT, fb, st + 4 * 260, tg2, tbe2, m5, out);
}